// round 14
// baseline (speedup 1.0000x reference)
#include <cuda_runtime.h>

#define B_    16
#define N_    400
#define P_    200
#define E_D   200
#define A_D   128
#define H_    8
#define PT    4      // pathways per block in kernel B
#define NCH   7      // gene chunks of 64 for kA/kB layout
#define CG    32     // genes per chunk in kC
#define NCHC  13     // kC chunks: 12 x 32 + 1 x 16

typedef unsigned long long u64;

// proj scratch: ulonglong2 at ((b*NCH + c)*64 + k)*32 + lane =
//   { u64(prj[gLo][2k],  prj[gHi][2k]),  u64(prj[gLo][2k+1], prj[gHi][2k+1]) }
// gLo = c*64+lane, gHi = gLo+32 (c<6); chunk 6: lane<8, gLo=384+lane, gHi=gLo+8.
__device__ ulonglong2 g_projP[B_ * NCH * 64 * 32];

// attn scratch (B, P, N) written by kB phase 2, consumed by kC.
__device__ float g_attn[B_ * P_ * N_];

// Wb duplicated pairs: staging (device) -> constant (LDC port, off L1).
__device__ u64 g_wbDup[A_D * H_];             // [a*8 + h] = (w, w)
__constant__ ulonglong2 c_wb4[A_D * H_ / 2];  // [a*4 + h2]: .x=head 2h2, .y=head 2h2+1

__device__ __forceinline__ u64 pack2(float x, float y) {
    u64 r; asm("mov.b64 %0, {%1, %2};" : "=l"(r) : "f"(x), "f"(y)); return r;
}
__device__ __forceinline__ void unpack2(u64 v, float& x, float& y) {
    asm("mov.b64 {%0, %1}, %2;" : "=f"(x), "=f"(y) : "l"(v));
}
__device__ __forceinline__ u64 fma2(u64 a, u64 b, u64 c) {
    u64 d; asm("fma.rn.f32x2 %0, %1, %2, %3;" : "=l"(d) : "l"(a), "l"(b), "l"(c)); return d;
}
__device__ __forceinline__ u64 add2(u64 a, u64 b) {
    u64 d; asm("add.rn.f32x2 %0, %1, %2;" : "=l"(d) : "l"(a), "l"(b)); return d;
}
__device__ __forceinline__ float tanh_ap(float x) {
    float y; asm("tanh.approx.f32 %0, %1;" : "=f"(y) : "f"(x)); return y;
}
__device__ __forceinline__ u64 tanh2(u64 v) {
    float x, y; unpack2(v, x, y);
    return pack2(tanh_ap(x), tanh_ap(y));
}

// ---------------------------------------------------------------------------
// Kernel W: duplicate Wb scalars into (w,w) pairs for f32x2 FMAs.
// ---------------------------------------------------------------------------
__global__ void kW(const float* __restrict__ Wb)
{
    int i = blockIdx.x * 256 + threadIdx.x;
    if (i < A_D * H_) {
        float v = Wb[i];
        g_wbDup[i] = pack2(v, v);
    }
}

// ---------------------------------------------------------------------------
// Kernel A: proj = emb_gene[omc] @ W0 + b0, scattered into gene-paired layout.
// ---------------------------------------------------------------------------
__global__ __launch_bounds__(128) void kA(
    const int* __restrict__ omc, const float* __restrict__ eg,
    const float* __restrict__ W0, const float* __restrict__ b0)
{
    __shared__ float EsT[E_D * 8];   // [e][r]
    __shared__ int idxs[8];
    const int R0 = blockIdx.x * 8;
    const int b  = R0 / N_;
    const int nb = R0 - b * N_;
    const int t  = threadIdx.x;

    if (t < 8) idxs[t] = omc[R0 + t];
    __syncthreads();
    for (int i = t; i < 8 * E_D; i += 128) {
        int r = i / E_D, e = i - r * E_D;
        EsT[e * 8 + r] = eg[(long)idxs[r] * E_D + e];
    }
    __syncthreads();

    const int k  = t & 63;           // a-pair: a = 2k, 2k+1
    const int rg = t >> 6;           // row group (4 rows each)
    const u64* W2 = (const u64*)W0;  // [e][64] pairs
    const u64  bias = ((const u64*)b0)[k];

    u64 acc[4];
#pragma unroll
    for (int r = 0; r < 4; r++) acc[r] = bias;

#pragma unroll 4
    for (int e = 0; e < E_D; e++) {
        u64 w = W2[e * 64 + k];
        const float* er = EsT + e * 8 + rg * 4;
        acc[0] = fma2(pack2(er[0], er[0]), w, acc[0]);
        acc[1] = fma2(pack2(er[1], er[1]), w, acc[1]);
        acc[2] = fma2(pack2(er[2], er[2]), w, acc[2]);
        acc[3] = fma2(pack2(er[3], er[3]), w, acc[3]);
    }

    float* pf = (float*)g_projP;
#pragma unroll
    for (int r = 0; r < 4; r++) {
        const int n = nb + rg * 4 + r;          // gene index within batch b
        const int chunk = n >> 6;
        const int idx   = n & 63;
        int lane, comp;
        if (chunk < 6) { lane = idx & 31; comp = idx >> 5; }
        else           { lane = idx & 7;  comp = idx >> 3; }
        // float layout of ulonglong2 cell: {aLo.gLo, aLo.gHi, aHi.gLo, aHi.gHi}
        const int fbase = (((b * NCH + chunk) * 64 + k) * 32 + lane) * 4 + comp;
        float x, y;
        unpack2(acc[r], x, y);
        pf[fbase]     = x;      // a = 2k
        pf[fbase + 2] = y;      // a = 2k+1
    }
}

// ---------------------------------------------------------------------------
// Kernel B (scores + softmax). Unchanged from R12/R13 (measured ~127us).
//
// SMEM floats:
//   sc    [0, 12800)       scores PT*H*N
//   epsQ  [12800, 13824)   2 groups x 128 a x {dupA u64, dupB u64}
//   sinv  [13824, 13856)
//   bbs   [13856, 13864)
// ---------------------------------------------------------------------------
#define SMEM_B_FLOATS 13864
#define SMEM_B_BYTES  (SMEM_B_FLOATS * 4)

extern __shared__ float smemB[];

#define STAGE_FMA(wc, T0, T1, T2, T3)                                   \
    do {                                                                \
        ulonglong2 wA = c_wb4[(wc) + 0];                                \
        accA[0] = fma2(T0, wA.x, accA[0]);                              \
        accB[0] = fma2(T1, wA.x, accB[0]);                              \
        accA[1] = fma2(T0, wA.y, accA[1]);                              \
        accB[1] = fma2(T1, wA.y, accB[1]);                              \
        ulonglong2 wB = c_wb4[(wc) + 1];                                \
        accA[2] = fma2(T0, wB.x, accA[2]);                              \
        accB[2] = fma2(T1, wB.x, accB[2]);                              \
        accA[3] = fma2(T0, wB.y, accA[3]);                              \
        accB[3] = fma2(T1, wB.y, accB[3]);                              \
        ulonglong2 wC = c_wb4[(wc) + 2];                                \
        accA[4] = fma2(T0, wC.x, accA[4]);                              \
        accB[4] = fma2(T1, wC.x, accB[4]);                              \
        accA[5] = fma2(T0, wC.y, accA[5]);                              \
        accB[5] = fma2(T1, wC.y, accB[5]);                              \
        ulonglong2 wD = c_wb4[(wc) + 3];                                \
        accA[6] = fma2(T0, wD.x, accA[6]);                              \
        accB[6] = fma2(T1, wD.x, accB[6]);                              \
        accA[7] = fma2(T0, wD.y, accA[7]);                              \
        accB[7] = fma2(T1, wD.y, accB[7]);                              \
        ulonglong2 wE = c_wb4[(wc) + 4];                                \
        accA[0] = fma2(T2, wE.x, accA[0]);                              \
        accB[0] = fma2(T3, wE.x, accB[0]);                              \
        accA[1] = fma2(T2, wE.y, accA[1]);                              \
        accB[1] = fma2(T3, wE.y, accB[1]);                              \
        ulonglong2 wF = c_wb4[(wc) + 5];                                \
        accA[2] = fma2(T2, wF.x, accA[2]);                              \
        accB[2] = fma2(T3, wF.x, accB[2]);                              \
        accA[3] = fma2(T2, wF.y, accA[3]);                              \
        accB[3] = fma2(T3, wF.y, accB[3]);                              \
        ulonglong2 wG = c_wb4[(wc) + 6];                                \
        accA[4] = fma2(T2, wG.x, accA[4]);                              \
        accB[4] = fma2(T3, wG.x, accB[4]);                              \
        accA[5] = fma2(T2, wG.y, accA[5]);                              \
        accB[5] = fma2(T3, wG.y, accB[5]);                              \
        ulonglong2 wH = c_wb4[(wc) + 7];                                \
        accA[6] = fma2(T2, wH.x, accA[6]);                              \
        accB[6] = fma2(T3, wH.x, accB[6]);                              \
        accA[7] = fma2(T2, wH.y, accA[7]);                              \
        accB[7] = fma2(T3, wH.y, accB[7]);                              \
    } while (0)

#define STAGE_TANH(L, epB, D0, D1, D2, D3)                              \
    do {                                                                \
        ulonglong2 e0 = *(const ulonglong2*)(epB);                      \
        D0 = tanh2(add2((L).x, e0.x));                                  \
        D1 = tanh2(add2((L).x, e0.y));                                  \
        ulonglong2 e1 = *(const ulonglong2*)((epB) + 16);               \
        D2 = tanh2(add2((L).y, e1.x));                                  \
        D3 = tanh2(add2((L).y, e1.y));                                  \
    } while (0)

__global__ __launch_bounds__(256, 3) void kB(
    const int* __restrict__ ptw, const float* __restrict__ ept,
    const float* __restrict__ bb)
{
    float* sc   = smemB;
    ulonglong2* epsQ = (ulonglong2*)(smemB + 12800);  // [group*128 + a]
    float* sinv = smemB + 13824;
    float* bbs  = smemB + 13856;

    const int bx   = blockIdx.x;
    const int b    = bx / 50;
    const int pt   = bx - b * 50;
    const int t    = threadIdx.x;
    const int w    = t >> 5;
    const int lane = t & 31;

    {
        float* ef = (float*)epsQ;
        for (int i = t; i < 1024; i += 256) {
            int g  = i >> 9;
            int a  = (i >> 2) & 127;
            int c4 = i & 3;
            int pl = g * 2 + (c4 >> 1);
            ef[(g * 128 + a) * 4 + c4] = ept[(long)ptw[pt * PT + pl] * A_D + a];
        }
    }
    if (t < 8) bbs[t] = bb[t];
    __syncthreads();

    {
        const int pairI = w & 1;
        float* scA = sc + (2 * pairI + 0) * H_ * N_;
        float* scB = sc + (2 * pairI + 1) * H_ * N_;
        const char* epBase = (const char*)(epsQ + pairI * 128);

        for (int c = w >> 1; c < NCH; c += 4) {
            u64 accA[H_], accB[H_];
#pragma unroll
            for (int h = 0; h < H_; h++) { accA[h] = 0ull; accB[h] = 0ull; }

            const char* ppB = (const char*)(g_projP + ((b * NCH + c) * 64) * 32 + lane);
            const char* epB = epBase;

            u64 T0, T1, T2, T3, U0, U1, U2, U3;
            {
                ulonglong2 L0 = *(const ulonglong2*)ppB;
                STAGE_TANH(L0, epB, T0, T1, T2, T3);
            }
            ulonglong2 L1 = *(const ulonglong2*)(ppB + 512);
            ulonglong2 L2 = *(const ulonglong2*)(ppB + 1024);
            ppB += 1536;
            epB += 32;

            int wc = 0;
#pragma unroll 2
            for (int s = 0; s < 62; s++) {
                STAGE_TANH(L1, epB, U0, U1, U2, U3);
                STAGE_FMA(wc, T0, T1, T2, T3);
                L1 = L2;
                L2 = *(const ulonglong2*)ppB;
                T0 = U0; T1 = U1; T2 = U2; T3 = U3;
                ppB += 512;
                epB += 32;
                wc += 8;
            }
            STAGE_TANH(L1, epB, U0, U1, U2, U3);
            STAGE_FMA(wc, T0, T1, T2, T3);
            STAGE_FMA(wc + 8, U0, U1, U2, U3);

            int geneA, geneB;
            bool valid;
            if (c < 6) { geneA = c * 64 + lane; geneB = geneA + 32; valid = true; }
            else       { geneA = 384 + (lane & 7); geneB = geneA + 8; valid = (lane < 8); }
            if (valid) {
#pragma unroll
                for (int h = 0; h < H_; h++) {
                    float xA, yA, xB, yB;
                    unpack2(accA[h], xA, yA);
                    unpack2(accB[h], xB, yB);
                    const float bh = bbs[h];
                    scA[h * N_ + geneA] = xA + bh;
                    scA[h * N_ + geneB] = yA + bh;
                    scB[h * N_ + geneA] = xB + bh;
                    scB[h * N_ + geneB] = yB + bh;
                }
            }
        }
    }
    __syncthreads();

    const int p    = w >> 1;
    const int half = w & 1;
    const int pg   = pt * PT + p;
    float* scp = sc + p * H_ * N_;
#pragma unroll
    for (int q = 0; q < 4; q++) {
        const int h = half * 4 + q;
        float* row = scp + h * N_;
        float m = -1e30f;
        for (int i = lane; i < N_; i += 32) m = fmaxf(m, row[i]);
#pragma unroll
        for (int o = 16; o; o >>= 1) m = fmaxf(m, __shfl_xor_sync(0xffffffffu, m, o));
        float s = 0.f;
        for (int i = lane; i < N_; i += 32) {
            float e = __expf(row[i] - m);
            row[i] = e;
            s += e;
        }
#pragma unroll
        for (int o = 16; o; o >>= 1) s += __shfl_xor_sync(0xffffffffu, s, o);
        if (lane == 0) sinv[p * H_ + h] = __fdividef(1.f, s);
    }
    __syncthreads();

    {
        float iv[H_];
#pragma unroll
        for (int h = 0; h < H_; h++) iv[h] = sinv[p * H_ + h];
        float* gap = g_attn + ((long)(b * P_) + pg) * N_;
        for (int i = lane; i < 200; i += 32) {
            const int n = half * 200 + i;
            float a = 0.f;
#pragma unroll
            for (int h = 0; h < H_; h++) a = fmaf(scp[h * N_ + n], iv[h], a);
            gap[n] = a;
        }
    }
}

// ---------------------------------------------------------------------------
// Kernel C (pooling, v3): out[b,pg,:] = sum_n attn[b,pg,n] * E[b,n,:]
// Block = (b, 8 pathways), 256 threads = 8 warps.
// Warp = (quad q = w>>2: 4 pathways, gene-quarter gq = w&3).
// DOUBLE-BUFFERED 32-gene chunks: stage chunk c+1 (direct omc broadcast LDG,
// no idxs smem) while computing chunk c; ONE barrier per chunk.
//
// SMEM floats:
//   buf0  [0, 6400)        32 genes x 200
//   buf1  [6400, 12800)    32 genes x 200
//   attnS [12800, 16000)   8 x 400
// = 64000 bytes -> 3 blocks/SM. Reduction reuses buf region after the loop.
// ---------------------------------------------------------------------------
#define SMEM_C_FLOATS 16000
#define SMEM_C_BYTES  (SMEM_C_FLOATS * 4)

__global__ __launch_bounds__(256, 3) void kC(
    const int* __restrict__ omc, const float* __restrict__ eg,
    float* __restrict__ out)
{
    float* attnS = smemB + 12800;

    const int bx   = blockIdx.x;
    const int b    = bx / 25;
    const int pt8  = bx - b * 25;       // pathway octet
    const int t    = threadIdx.x;
    const int w    = t >> 5;
    const int lane = t & 31;
    const int q    = w >> 2;            // pathway quad 0..1
    const int gq   = w & 3;             // gene quarter

    const ulonglong2* egq = (const ulonglong2*)eg;   // 50 u128 per vocab row
    ulonglong2* bufq[2] = { (ulonglong2*)smemB, (ulonglong2*)(smemB + 6400) };
    const int* omcb = omc + b * N_;

    // stage attn for 8 pathways (3200 floats)
    {
        const float4* gA0 = (const float4*)(g_attn + ((long)(b * P_) + pt8 * 8) * N_);
        float4* aS = (float4*)attnS;
        for (int i = t; i < 800; i += 256) aS[i] = gA0[i];
    }

    // stage chunk 0 (genes w, w+8, w+16, w+24)
    {
        ulonglong2* dst0 = bufq[0];
        int idx4[4]; int m = 0;
#pragma unroll
        for (int g = w; g < CG; g += 8) idx4[m++] = omcb[g];
        m = 0;
#pragma unroll
        for (int g = w; g < CG; g += 8) {
            const ulonglong2* src = egq + (long)idx4[m++] * 50;
            ulonglong2* dst = dst0 + g * 50;
            dst[lane] = src[lane];
            if (lane < 18) dst[32 + lane] = src[32 + lane];
        }
    }
    __syncthreads();

    const float* ap0 = attnS + (q * 4 + 0) * N_;
    const float* ap1 = attnS + (q * 4 + 1) * N_;
    const float* ap2 = attnS + (q * 4 + 2) * N_;
    const float* ap3 = attnS + (q * 4 + 3) * N_;

    u64 a00=0, a01=0, a02=0, a03=0;
    u64 a10=0, a11=0, a12=0, a13=0;
    u64 a20=0, a21=0, a22=0, a23=0;
    u64 a30=0, a31=0, a32=0, a33=0;

    for (int c = 0; c < NCHC; c++) {
        const int n0 = c * CG;
        const int cnt = min(CG, N_ - n0);
        ulonglong2* cur = bufq[c & 1];

        // stage next chunk into the other buffer (overlaps with compute)
        if (c < NCHC - 1) {
            const int nn0 = n0 + CG;
            const int ncnt = min(CG, N_ - nn0);
            ulonglong2* nxt = bufq[(c & 1) ^ 1];
            int idx4[4]; int m = 0;
            for (int g = w; g < ncnt; g += 8) idx4[m++] = omcb[nn0 + g];
            m = 0;
            for (int g = w; g < ncnt; g += 8) {
                const ulonglong2* src = egq + (long)idx4[m++] * 50;
                ulonglong2* dst = nxt + g * 50;
                dst[lane] = src[lane];
                if (lane < 18) dst[32 + lane] = src[32 + lane];
            }
        }

        // compute chunk c: genes gq, gq+4, ...
        for (int n = gq; n < cnt; n += 4) {
            const int na = n0 + n;
            u64 v0 = pack2(ap0[na], ap0[na]);
            u64 v1 = pack2(ap1[na], ap1[na]);
            u64 v2 = pack2(ap2[na], ap2[na]);
            u64 v3 = pack2(ap3[na], ap3[na]);
            ulonglong2 e0 = cur[n * 50 + lane];
            a00 = fma2(e0.x, v0, a00);  a01 = fma2(e0.y, v0, a01);
            a10 = fma2(e0.x, v1, a10);  a11 = fma2(e0.y, v1, a11);
            a20 = fma2(e0.x, v2, a20);  a21 = fma2(e0.y, v2, a21);
            a30 = fma2(e0.x, v3, a30);  a31 = fma2(e0.y, v3, a31);
            if (lane < 18) {
                ulonglong2 e1 = cur[n * 50 + 32 + lane];
                a02 = fma2(e1.x, v0, a02);  a03 = fma2(e1.y, v0, a03);
                a12 = fma2(e1.x, v1, a12);  a13 = fma2(e1.y, v1, a13);
                a22 = fma2(e1.x, v2, a22);  a23 = fma2(e1.y, v2, a23);
                a32 = fma2(e1.x, v3, a32);  a33 = fma2(e1.y, v3, a33);
            }
        }
        __syncthreads();   // next-stage writes done AND compute reads done
    }

    // reduction over gene-quarters via smem (buf region free now).
    // red layout: [(q*3 + (gq-1))*4 + p] rows of 50 u128 -> 24 x 50 u128
    ulonglong2* red = (ulonglong2*)smemB;
    if (gq != 0) {
        ulonglong2* r0 = red + ((q * 3 + (gq - 1)) * 4 + 0) * 50;
        ulonglong2* r1 = red + ((q * 3 + (gq - 1)) * 4 + 1) * 50;
        ulonglong2* r2 = red + ((q * 3 + (gq - 1)) * 4 + 2) * 50;
        ulonglong2* r3 = red + ((q * 3 + (gq - 1)) * 4 + 3) * 50;
        ulonglong2 s;
        s.x = a00; s.y = a01; r0[lane] = s;
        s.x = a10; s.y = a11; r1[lane] = s;
        s.x = a20; s.y = a21; r2[lane] = s;
        s.x = a30; s.y = a31; r3[lane] = s;
        if (lane < 18) {
            s.x = a02; s.y = a03; r0[32 + lane] = s;
            s.x = a12; s.y = a13; r1[32 + lane] = s;
            s.x = a22; s.y = a23; r2[32 + lane] = s;
            s.x = a32; s.y = a33; r3[32 + lane] = s;
        }
    }
    __syncthreads();
    if (gq == 0) {
#pragma unroll
        for (int j = 0; j < 3; j++) {
            const ulonglong2* r0 = red + ((q * 3 + j) * 4 + 0) * 50;
            const ulonglong2* r1 = red + ((q * 3 + j) * 4 + 1) * 50;
            const ulonglong2* r2 = red + ((q * 3 + j) * 4 + 2) * 50;
            const ulonglong2* r3 = red + ((q * 3 + j) * 4 + 3) * 50;
            ulonglong2 s;
            s = r0[lane]; a00 = add2(a00, s.x); a01 = add2(a01, s.y);
            s = r1[lane]; a10 = add2(a10, s.x); a11 = add2(a11, s.y);
            s = r2[lane]; a20 = add2(a20, s.x); a21 = add2(a21, s.y);
            s = r3[lane]; a30 = add2(a30, s.x); a31 = add2(a31, s.y);
            if (lane < 18) {
                s = r0[32 + lane]; a02 = add2(a02, s.x); a03 = add2(a03, s.y);
                s = r1[32 + lane]; a12 = add2(a12, s.x); a13 = add2(a13, s.y);
                s = r2[32 + lane]; a22 = add2(a22, s.x); a23 = add2(a23, s.y);
                s = r3[32 + lane]; a32 = add2(a32, s.x); a33 = add2(a33, s.y);
            }
        }
        const int pg0 = pt8 * 8 + q * 4;
        ulonglong2* op0 = (ulonglong2*)(out + (long)(b * P_ + pg0 + 0) * E_D);
        ulonglong2* op1 = (ulonglong2*)(out + (long)(b * P_ + pg0 + 1) * E_D);
        ulonglong2* op2 = (ulonglong2*)(out + (long)(b * P_ + pg0 + 2) * E_D);
        ulonglong2* op3 = (ulonglong2*)(out + (long)(b * P_ + pg0 + 3) * E_D);
        ulonglong2 s;
        s.x = a00; s.y = a01; op0[lane] = s;
        s.x = a10; s.y = a11; op1[lane] = s;
        s.x = a20; s.y = a21; op2[lane] = s;
        s.x = a30; s.y = a31; op3[lane] = s;
        if (lane < 18) {
            s.x = a02; s.y = a03; op0[32 + lane] = s;
            s.x = a12; s.y = a13; op1[32 + lane] = s;
            s.x = a22; s.y = a23; op2[32 + lane] = s;
            s.x = a32; s.y = a33; op3[32 + lane] = s;
        }
    }
}

// ---------------------------------------------------------------------------
extern "C" void kernel_launch(void* const* d_in, const int* in_sizes, int n_in,
                              void* d_out, int out_size)
{
    const int*   omc = (const int*)  d_in[0];
    const int*   ptw = (const int*)  d_in[1];
    const float* eg  = (const float*)d_in[2];
    const float* ept = (const float*)d_in[3];
    const float* W0  = (const float*)d_in[4];
    const float* b0  = (const float*)d_in[5];
    const float* Wb  = (const float*)d_in[6];
    const float* bb  = (const float*)d_in[7];
    float* out = (float*)d_out;

    kW<<<4, 256>>>(Wb);
    void* srcp = nullptr;
    cudaGetSymbolAddress(&srcp, g_wbDup);
    void* dstp = nullptr;
    cudaGetSymbolAddress(&dstp, c_wb4);
    cudaMemcpyAsync(dstp, srcp, sizeof(u64) * A_D * H_,
                    cudaMemcpyDeviceToDevice, 0);

    kA<<<(B_ * N_) / 8, 128>>>(omc, eg, W0, b0);

    cudaFuncSetAttribute(kB, cudaFuncAttributeMaxDynamicSharedMemorySize,
                         SMEM_B_BYTES);
    kB<<<B_ * (P_ / PT), 256, SMEM_B_BYTES>>>(ptw, ept, bb);

    cudaFuncSetAttribute(kC, cudaFuncAttributeMaxDynamicSharedMemorySize,
                         SMEM_C_BYTES);
    kC<<<B_ * (P_ / 8), 256, SMEM_C_BYTES>>>(omc, eg, out);
}

// round 15
// speedup vs baseline: 1.0808x; 1.0808x over previous
#include <cuda_runtime.h>

#define B_    16
#define N_    400
#define P_    200
#define E_D   200
#define A_D   128
#define H_    8
#define PT    4      // pathways per block in kernel B
#define NCH   7      // gene chunks of 64 for kA/kB layout

typedef unsigned long long u64;

// proj scratch: ulonglong2 at ((b*NCH + c)*64 + k)*32 + lane =
//   { u64(prj[gLo][2k],  prj[gHi][2k]),  u64(prj[gLo][2k+1], prj[gHi][2k+1]) }
// gLo = c*64+lane, gHi = gLo+32 (c<6); chunk 6: lane<8, gLo=384+lane, gHi=gLo+8.
__device__ ulonglong2 g_projP[B_ * NCH * 64 * 32];

// attn scratch (B, P, N) written by kB phase 2, consumed by kC.
__device__ float g_attn[B_ * P_ * N_];

// Wb duplicated pairs: staging (device) -> constant (heads 0-3 used there).
__device__ u64 g_wbDup[A_D * H_];             // [a*8 + h] = (w, w)
__constant__ ulonglong2 c_wb4[A_D * H_ / 2];  // [a*4 + h2]: .x=head 2h2, .y=head 2h2+1

__device__ __forceinline__ u64 pack2(float x, float y) {
    u64 r; asm("mov.b64 %0, {%1, %2};" : "=l"(r) : "f"(x), "f"(y)); return r;
}
__device__ __forceinline__ void unpack2(u64 v, float& x, float& y) {
    asm("mov.b64 {%0, %1}, %2;" : "=f"(x), "=f"(y) : "l"(v));
}
__device__ __forceinline__ u64 fma2(u64 a, u64 b, u64 c) {
    u64 d; asm("fma.rn.f32x2 %0, %1, %2, %3;" : "=l"(d) : "l"(a), "l"(b), "l"(c)); return d;
}
__device__ __forceinline__ u64 add2(u64 a, u64 b) {
    u64 d; asm("add.rn.f32x2 %0, %1, %2;" : "=l"(d) : "l"(a), "l"(b)); return d;
}
__device__ __forceinline__ float tanh_ap(float x) {
    float y; asm("tanh.approx.f32 %0, %1;" : "=f"(y) : "f"(x)); return y;
}
__device__ __forceinline__ u64 tanh2(u64 v) {
    float x, y; unpack2(v, x, y);
    return pack2(tanh_ap(x), tanh_ap(y));
}

// ---------------------------------------------------------------------------
// Kernel W: duplicate Wb scalars into (w,w) pairs for f32x2 FMAs.
// ---------------------------------------------------------------------------
__global__ void kW(const float* __restrict__ Wb)
{
    int i = blockIdx.x * 256 + threadIdx.x;
    if (i < A_D * H_) {
        float v = Wb[i];
        g_wbDup[i] = pack2(v, v);
    }
}

// ---------------------------------------------------------------------------
// Kernel A: proj = emb_gene[omc] @ W0 + b0, scattered into gene-paired layout.
// ---------------------------------------------------------------------------
__global__ __launch_bounds__(128) void kA(
    const int* __restrict__ omc, const float* __restrict__ eg,
    const float* __restrict__ W0, const float* __restrict__ b0)
{
    __shared__ float EsT[E_D * 8];   // [e][r]
    __shared__ int idxs[8];
    const int R0 = blockIdx.x * 8;
    const int b  = R0 / N_;
    const int nb = R0 - b * N_;
    const int t  = threadIdx.x;

    if (t < 8) idxs[t] = omc[R0 + t];
    __syncthreads();
    for (int i = t; i < 8 * E_D; i += 128) {
        int r = i / E_D, e = i - r * E_D;
        EsT[e * 8 + r] = eg[(long)idxs[r] * E_D + e];
    }
    __syncthreads();

    const int k  = t & 63;           // a-pair: a = 2k, 2k+1
    const int rg = t >> 6;           // row group (4 rows each)
    const u64* W2 = (const u64*)W0;  // [e][64] pairs
    const u64  bias = ((const u64*)b0)[k];

    u64 acc[4];
#pragma unroll
    for (int r = 0; r < 4; r++) acc[r] = bias;

#pragma unroll 4
    for (int e = 0; e < E_D; e++) {
        u64 w = W2[e * 64 + k];
        const float* er = EsT + e * 8 + rg * 4;
        acc[0] = fma2(pack2(er[0], er[0]), w, acc[0]);
        acc[1] = fma2(pack2(er[1], er[1]), w, acc[1]);
        acc[2] = fma2(pack2(er[2], er[2]), w, acc[2]);
        acc[3] = fma2(pack2(er[3], er[3]), w, acc[3]);
    }

    float* pf = (float*)g_projP;
#pragma unroll
    for (int r = 0; r < 4; r++) {
        const int n = nb + rg * 4 + r;          // gene index within batch b
        const int chunk = n >> 6;
        const int idx   = n & 63;
        int lane, comp;
        if (chunk < 6) { lane = idx & 31; comp = idx >> 5; }
        else           { lane = idx & 7;  comp = idx >> 3; }
        // float layout of ulonglong2 cell: {aLo.gLo, aLo.gHi, aHi.gLo, aHi.gHi}
        const int fbase = (((b * NCH + chunk) * 64 + k) * 32 + lane) * 4 + comp;
        float x, y;
        unpack2(acc[r], x, y);
        pf[fbase]     = x;      // a = 2k
        pf[fbase + 2] = y;      // a = 2k+1
    }
}

// ---------------------------------------------------------------------------
// Kernel B (scores + softmax). Block = (b, 4 pathways), 256 threads, 8 warps.
// PORT-BALANCED Wb: heads 0-3 from constant (8 LDC.128/stage = 64cyc, LDC
// floor 8), heads 4-7 from smem (8 LDS.128/stage on the lightly-used L1 port).
// Previously all 16 LDC.128/stage = 128cyc on the half-rate constant port
// was the binding pipe (2x FMA).
//
// SMEM floats:
//   sc    [0, 12800)       scores PT*H*N
//   epsQ  [12800, 13824)   2 groups x 128 a x {dupA u64, dupB u64}
//   wbS   [13824, 14848)   128 a x heads 4..7 dup pairs (2 u128 per a)
//   sinv  [14848, 14880)
//   bbs   [14880, 14888)
// = 59552 bytes -> 3 blocks/SM
// ---------------------------------------------------------------------------
#define SMEM_B_FLOATS 14888
#define SMEM_B_BYTES  (SMEM_B_FLOATS * 4)

extern __shared__ float smemB[];

// wc: constant base (advances 8/stage); wbB: smem byte ptr (advances 64/stage).
// Even a: heads0-3 c_wb4[wc+0..1], heads4-7 smem [wbB+0,+16].
// Odd  a: heads0-3 c_wb4[wc+4..5], heads4-7 smem [wbB+32,+48].
#define STAGE_FMA(wc, wbB, T0, T1, T2, T3)                              \
    do {                                                                \
        ulonglong2 wA = c_wb4[(wc) + 0];                                \
        accA[0] = fma2(T0, wA.x, accA[0]);                              \
        accB[0] = fma2(T1, wA.x, accB[0]);                              \
        accA[1] = fma2(T0, wA.y, accA[1]);                              \
        accB[1] = fma2(T1, wA.y, accB[1]);                              \
        ulonglong2 wB = c_wb4[(wc) + 1];                                \
        accA[2] = fma2(T0, wB.x, accA[2]);                              \
        accB[2] = fma2(T1, wB.x, accB[2]);                              \
        accA[3] = fma2(T0, wB.y, accA[3]);                              \
        accB[3] = fma2(T1, wB.y, accB[3]);                              \
        ulonglong2 wC = *(const ulonglong2*)(wbB);                      \
        accA[4] = fma2(T0, wC.x, accA[4]);                              \
        accB[4] = fma2(T1, wC.x, accB[4]);                              \
        accA[5] = fma2(T0, wC.y, accA[5]);                              \
        accB[5] = fma2(T1, wC.y, accB[5]);                              \
        ulonglong2 wD = *(const ulonglong2*)((wbB) + 16);               \
        accA[6] = fma2(T0, wD.x, accA[6]);                              \
        accB[6] = fma2(T1, wD.x, accB[6]);                              \
        accA[7] = fma2(T0, wD.y, accA[7]);                              \
        accB[7] = fma2(T1, wD.y, accB[7]);                              \
        ulonglong2 wE = c_wb4[(wc) + 4];                                \
        accA[0] = fma2(T2, wE.x, accA[0]);                              \
        accB[0] = fma2(T3, wE.x, accB[0]);                              \
        accA[1] = fma2(T2, wE.y, accA[1]);                              \
        accB[1] = fma2(T3, wE.y, accB[1]);                              \
        ulonglong2 wF = c_wb4[(wc) + 5];                                \
        accA[2] = fma2(T2, wF.x, accA[2]);                              \
        accB[2] = fma2(T3, wF.x, accB[2]);                              \
        accA[3] = fma2(T2, wF.y, accA[3]);                              \
        accB[3] = fma2(T3, wF.y, accB[3]);                              \
        ulonglong2 wG = *(const ulonglong2*)((wbB) + 32);               \
        accA[4] = fma2(T2, wG.x, accA[4]);                              \
        accB[4] = fma2(T3, wG.x, accB[4]);                              \
        accA[5] = fma2(T2, wG.y, accA[5]);                              \
        accB[5] = fma2(T3, wG.y, accB[5]);                              \
        ulonglong2 wH = *(const ulonglong2*)((wbB) + 48);               \
        accA[6] = fma2(T2, wH.x, accA[6]);                              \
        accB[6] = fma2(T3, wH.x, accB[6]);                              \
        accA[7] = fma2(T2, wH.y, accA[7]);                              \
        accB[7] = fma2(T3, wH.y, accB[7]);                              \
    } while (0)

#define STAGE_TANH(L, epB, D0, D1, D2, D3)                              \
    do {                                                                \
        ulonglong2 e0 = *(const ulonglong2*)(epB);                      \
        D0 = tanh2(add2((L).x, e0.x));                                  \
        D1 = tanh2(add2((L).x, e0.y));                                  \
        ulonglong2 e1 = *(const ulonglong2*)((epB) + 16);               \
        D2 = tanh2(add2((L).y, e1.x));                                  \
        D3 = tanh2(add2((L).y, e1.y));                                  \
    } while (0)

__global__ __launch_bounds__(256, 3) void kB(
    const int* __restrict__ ptw, const float* __restrict__ ept,
    const float* __restrict__ Wb, const float* __restrict__ bb)
{
    float* sc   = smemB;
    ulonglong2* epsQ = (ulonglong2*)(smemB + 12800);  // [group*128 + a]
    u64*   wbS  = (u64*)(smemB + 13824);              // [a*4 + (h-4)]
    float* sinv = smemB + 14848;
    float* bbs  = smemB + 14880;

    const int bx   = blockIdx.x;
    const int b    = bx / 50;
    const int pt   = bx - b * 50;
    const int t    = threadIdx.x;
    const int w    = t >> 5;
    const int lane = t & 31;

    // ---- init loads -------------------------------------------------------
    {
        float* ef = (float*)epsQ;
        for (int i = t; i < 1024; i += 256) {
            int g  = i >> 9;
            int a  = (i >> 2) & 127;
            int c4 = i & 3;
            int pl = g * 2 + (c4 >> 1);
            ef[(g * 128 + a) * 4 + c4] = ept[(long)ptw[pt * PT + pl] * A_D + a];
        }
    }
    // wbS: heads 4..7 duplicated pairs, [a*4 + j], j = h-4
    for (int i = t; i < 512; i += 256) {
        int a = i >> 2, j = i & 3;
        float v = Wb[a * H_ + 4 + j];
        wbS[i] = pack2(v, v);
    }
    if (t < 8) bbs[t] = bb[t];
    __syncthreads();

    // ---- Phase 1: scores, pipelined stages, Wb split constant/smem --------
    {
        const int pairI = w & 1;
        float* scA = sc + (2 * pairI + 0) * H_ * N_;
        float* scB = sc + (2 * pairI + 1) * H_ * N_;
        const char* epBase = (const char*)(epsQ + pairI * 128);
        const char* wbBase = (const char*)wbS;

        for (int c = w >> 1; c < NCH; c += 4) {
            u64 accA[H_], accB[H_];
#pragma unroll
            for (int h = 0; h < H_; h++) { accA[h] = 0ull; accB[h] = 0ull; }

            const char* ppB = (const char*)(g_projP + ((b * NCH + c) * 64) * 32 + lane);
            const char* epB = epBase;
            const char* wbB = wbBase;

            u64 T0, T1, T2, T3, U0, U1, U2, U3;
            {
                ulonglong2 L0 = *(const ulonglong2*)ppB;
                STAGE_TANH(L0, epB, T0, T1, T2, T3);
            }
            ulonglong2 L1 = *(const ulonglong2*)(ppB + 512);
            ulonglong2 L2 = *(const ulonglong2*)(ppB + 1024);
            ppB += 1536;
            epB += 32;

            int wc = 0;
#pragma unroll 2
            for (int s = 0; s < 62; s++) {
                STAGE_TANH(L1, epB, U0, U1, U2, U3);     // tanh for s+1
                STAGE_FMA(wc, wbB, T0, T1, T2, T3);      // FMA  for s
                L1 = L2;
                L2 = *(const ulonglong2*)ppB;            // load s+3
                T0 = U0; T1 = U1; T2 = U2; T3 = U3;
                ppB += 512;
                epB += 32;
                wc += 8;
                wbB += 64;
            }
            STAGE_TANH(L1, epB, U0, U1, U2, U3);
            STAGE_FMA(wc, wbB, T0, T1, T2, T3);
            STAGE_FMA(wc + 8, wbB + 64, U0, U1, U2, U3);

            int geneA, geneB;
            bool valid;
            if (c < 6) { geneA = c * 64 + lane; geneB = geneA + 32; valid = true; }
            else       { geneA = 384 + (lane & 7); geneB = geneA + 8; valid = (lane < 8); }
            if (valid) {
#pragma unroll
                for (int h = 0; h < H_; h++) {
                    float xA, yA, xB, yB;
                    unpack2(accA[h], xA, yA);
                    unpack2(accB[h], xB, yB);
                    const float bh = bbs[h];
                    scA[h * N_ + geneA] = xA + bh;
                    scA[h * N_ + geneB] = yA + bh;
                    scB[h * N_ + geneA] = xB + bh;
                    scB[h * N_ + geneB] = yB + bh;
                }
            }
        }
    }
    __syncthreads();

    // ---- Phase 2: softmax over n per head; attn = sum_h -> g_attn ---------
    const int p    = w >> 1;
    const int half = w & 1;
    const int pg   = pt * PT + p;
    float* scp = sc + p * H_ * N_;
#pragma unroll
    for (int q = 0; q < 4; q++) {
        const int h = half * 4 + q;
        float* row = scp + h * N_;
        float m = -1e30f;
        for (int i = lane; i < N_; i += 32) m = fmaxf(m, row[i]);
#pragma unroll
        for (int o = 16; o; o >>= 1) m = fmaxf(m, __shfl_xor_sync(0xffffffffu, m, o));
        float s = 0.f;
        for (int i = lane; i < N_; i += 32) {
            float e = __expf(row[i] - m);
            row[i] = e;
            s += e;
        }
#pragma unroll
        for (int o = 16; o; o >>= 1) s += __shfl_xor_sync(0xffffffffu, s, o);
        if (lane == 0) sinv[p * H_ + h] = __fdividef(1.f, s);
    }
    __syncthreads();

    {
        float iv[H_];
#pragma unroll
        for (int h = 0; h < H_; h++) iv[h] = sinv[p * H_ + h];
        float* gap = g_attn + ((long)(b * P_) + pg) * N_;
        for (int i = lane; i < 200; i += 32) {
            const int n = half * 200 + i;
            float a = 0.f;
#pragma unroll
            for (int h = 0; h < H_; h++) a = fmaf(scp[h * N_ + n], iv[h], a);
            gap[n] = a;
        }
    }
}

// ---------------------------------------------------------------------------
// Kernel C (pooling, v2 — R13 proven 48.6us): out = attn @ E
// Block = (b, 8 pathways), 256 threads = 8 warps.
// Warp = (quad q = w>>2: 4 pathways, gene-quarter gq = w&3).
//
// SMEM floats:
//   Es    [0, 12800)       64 genes x 200 floats
//   attnS [12800, 16000)   8 x 400
//   idxs  [16000, 16064)
// = 64256 bytes -> 3 blocks/SM
// ---------------------------------------------------------------------------
#define SMEM_C_FLOATS 16064
#define SMEM_C_BYTES  (SMEM_C_FLOATS * 4)

__global__ __launch_bounds__(256, 3) void kC(
    const int* __restrict__ omc, const float* __restrict__ eg,
    float* __restrict__ out)
{
    float* Es    = smemB;
    float* attnS = smemB + 12800;
    int*   idxs  = (int*)(smemB + 16000);

    const int bx   = blockIdx.x;
    const int b    = bx / 25;
    const int pt8  = bx - b * 25;       // pathway octet
    const int t    = threadIdx.x;
    const int w    = t >> 5;
    const int lane = t & 31;
    const int q    = w >> 2;            // pathway quad 0..1
    const int gq   = w & 3;             // gene quarter

    // stage attn for 8 pathways (3200 floats)
    {
        const float4* gA0 = (const float4*)(g_attn + ((long)(b * P_) + pt8 * 8) * N_);
        float4* aS = (float4*)attnS;
        for (int i = t; i < 800; i += 256) aS[i] = gA0[i];
    }

    const float* ap0 = attnS + (q * 4 + 0) * N_;
    const float* ap1 = attnS + (q * 4 + 1) * N_;
    const float* ap2 = attnS + (q * 4 + 2) * N_;
    const float* ap3 = attnS + (q * 4 + 3) * N_;

    const ulonglong2* egq = (const ulonglong2*)eg;   // 50 u128 per vocab row
    ulonglong2* Esq = (ulonglong2*)Es;               // 3200 u128

    u64 a00=0, a01=0, a02=0, a03=0;
    u64 a10=0, a11=0, a12=0, a13=0;
    u64 a20=0, a21=0, a22=0, a23=0;
    u64 a30=0, a31=0, a32=0, a33=0;

    for (int c = 0; c < NCH; c++) {
        const int n0 = c * 64;
        const int cnt = min(64, N_ - n0);
        __syncthreads();
        if (t < cnt) idxs[t] = omc[b * N_ + n0 + t];
        __syncthreads();
        for (int g = w; g < cnt; g += 8) {
            const ulonglong2* src = egq + (long)idxs[g] * 50;
            ulonglong2* dst = Esq + g * 50;
            dst[lane] = src[lane];
            if (lane < 18) dst[32 + lane] = src[32 + lane];
        }
        __syncthreads();

        for (int n = gq; n < cnt; n += 4) {
            const int na = n0 + n;
            u64 v0 = pack2(ap0[na], ap0[na]);
            u64 v1 = pack2(ap1[na], ap1[na]);
            u64 v2 = pack2(ap2[na], ap2[na]);
            u64 v3 = pack2(ap3[na], ap3[na]);
            ulonglong2 e0 = Esq[n * 50 + lane];
            a00 = fma2(e0.x, v0, a00);  a01 = fma2(e0.y, v0, a01);
            a10 = fma2(e0.x, v1, a10);  a11 = fma2(e0.y, v1, a11);
            a20 = fma2(e0.x, v2, a20);  a21 = fma2(e0.y, v2, a21);
            a30 = fma2(e0.x, v3, a30);  a31 = fma2(e0.y, v3, a31);
            if (lane < 18) {
                ulonglong2 e1 = Esq[n * 50 + 32 + lane];
                a02 = fma2(e1.x, v0, a02);  a03 = fma2(e1.y, v0, a03);
                a12 = fma2(e1.x, v1, a12);  a13 = fma2(e1.y, v1, a13);
                a22 = fma2(e1.x, v2, a22);  a23 = fma2(e1.y, v2, a23);
                a32 = fma2(e1.x, v3, a32);  a33 = fma2(e1.y, v3, a33);
            }
        }
    }
    __syncthreads();   // Es region free; reuse for reduction

    ulonglong2* red = Esq;
    if (gq != 0) {
        ulonglong2* r0 = red + ((q * 3 + (gq - 1)) * 4 + 0) * 50;
        ulonglong2* r1 = red + ((q * 3 + (gq - 1)) * 4 + 1) * 50;
        ulonglong2* r2 = red + ((q * 3 + (gq - 1)) * 4 + 2) * 50;
        ulonglong2* r3 = red + ((q * 3 + (gq - 1)) * 4 + 3) * 50;
        ulonglong2 s;
        s.x = a00; s.y = a01; r0[lane] = s;
        s.x = a10; s.y = a11; r1[lane] = s;
        s.x = a20; s.y = a21; r2[lane] = s;
        s.x = a30; s.y = a31; r3[lane] = s;
        if (lane < 18) {
            s.x = a02; s.y = a03; r0[32 + lane] = s;
            s.x = a12; s.y = a13; r1[32 + lane] = s;
            s.x = a22; s.y = a23; r2[32 + lane] = s;
            s.x = a32; s.y = a33; r3[32 + lane] = s;
        }
    }
    __syncthreads();
    if (gq == 0) {
#pragma unroll
        for (int j = 0; j < 3; j++) {
            const ulonglong2* r0 = red + ((q * 3 + j) * 4 + 0) * 50;
            const ulonglong2* r1 = red + ((q * 3 + j) * 4 + 1) * 50;
            const ulonglong2* r2 = red + ((q * 3 + j) * 4 + 2) * 50;
            const ulonglong2* r3 = red + ((q * 3 + j) * 4 + 3) * 50;
            ulonglong2 s;
            s = r0[lane]; a00 = add2(a00, s.x); a01 = add2(a01, s.y);
            s = r1[lane]; a10 = add2(a10, s.x); a11 = add2(a11, s.y);
            s = r2[lane]; a20 = add2(a20, s.x); a21 = add2(a21, s.y);
            s = r3[lane]; a30 = add2(a30, s.x); a31 = add2(a31, s.y);
            if (lane < 18) {
                s = r0[32 + lane]; a02 = add2(a02, s.x); a03 = add2(a03, s.y);
                s = r1[32 + lane]; a12 = add2(a12, s.x); a13 = add2(a13, s.y);
                s = r2[32 + lane]; a22 = add2(a22, s.x); a23 = add2(a23, s.y);
                s = r3[32 + lane]; a32 = add2(a32, s.x); a33 = add2(a33, s.y);
            }
        }
        const int pg0 = pt8 * 8 + q * 4;
        ulonglong2* op0 = (ulonglong2*)(out + (long)(b * P_ + pg0 + 0) * E_D);
        ulonglong2* op1 = (ulonglong2*)(out + (long)(b * P_ + pg0 + 1) * E_D);
        ulonglong2* op2 = (ulonglong2*)(out + (long)(b * P_ + pg0 + 2) * E_D);
        ulonglong2* op3 = (ulonglong2*)(out + (long)(b * P_ + pg0 + 3) * E_D);
        ulonglong2 s;
        s.x = a00; s.y = a01; op0[lane] = s;
        s.x = a10; s.y = a11; op1[lane] = s;
        s.x = a20; s.y = a21; op2[lane] = s;
        s.x = a30; s.y = a31; op3[lane] = s;
        if (lane < 18) {
            s.x = a02; s.y = a03; op0[32 + lane] = s;
            s.x = a12; s.y = a13; op1[32 + lane] = s;
            s.x = a22; s.y = a23; op2[32 + lane] = s;
            s.x = a32; s.y = a33; op3[32 + lane] = s;
        }
    }
}

// ---------------------------------------------------------------------------
extern "C" void kernel_launch(void* const* d_in, const int* in_sizes, int n_in,
                              void* d_out, int out_size)
{
    const int*   omc = (const int*)  d_in[0];
    const int*   ptw = (const int*)  d_in[1];
    const float* eg  = (const float*)d_in[2];
    const float* ept = (const float*)d_in[3];
    const float* W0  = (const float*)d_in[4];
    const float* b0  = (const float*)d_in[5];
    const float* Wb  = (const float*)d_in[6];
    const float* bb  = (const float*)d_in[7];
    float* out = (float*)d_out;

    kW<<<4, 256>>>(Wb);
    void* srcp = nullptr;
    cudaGetSymbolAddress(&srcp, g_wbDup);
    void* dstp = nullptr;
    cudaGetSymbolAddress(&dstp, c_wb4);
    cudaMemcpyAsync(dstp, srcp, sizeof(u64) * A_D * H_,
                    cudaMemcpyDeviceToDevice, 0);

    kA<<<(B_ * N_) / 8, 128>>>(omc, eg, W0, b0);

    cudaFuncSetAttribute(kB, cudaFuncAttributeMaxDynamicSharedMemorySize,
                         SMEM_B_BYTES);
    kB<<<B_ * (P_ / PT), 256, SMEM_B_BYTES>>>(ptw, ept, Wb, bb);

    cudaFuncSetAttribute(kC, cudaFuncAttributeMaxDynamicSharedMemorySize,
                         SMEM_C_BYTES);
    kC<<<B_ * (P_ / 8), 256, SMEM_C_BYTES>>>(omc, eg, out);
}

// round 16
// speedup vs baseline: 1.0925x; 1.0108x over previous
#include <cuda_runtime.h>

#define B_    16
#define N_    400
#define P_    200
#define E_D   200
#define A_D   128
#define H_    8
#define PT    4      // pathways per block in kernel B
#define NCH   7      // gene chunks of 64 for kA/kB layout

typedef unsigned long long u64;

// proj scratch: ulonglong2 at ((b*NCH + c)*64 + k)*32 + lane =
//   { u64(prj[gLo][2k],  prj[gHi][2k]),  u64(prj[gLo][2k+1], prj[gHi][2k+1]) }
// gLo = c*64+lane, gHi = gLo+32 (c<6); chunk 6: lane<8, gLo=384+lane, gHi=gLo+8.
__device__ ulonglong2 g_projP[B_ * NCH * 64 * 32];

// attn scratch (B, P, N) written by kB phase 2, consumed by kC.
__device__ float g_attn[B_ * P_ * N_];

// Wb duplicated pairs: staging (device) -> constant (heads 0-3 used there).
__device__ u64 g_wbDup[A_D * H_];             // [a*8 + h] = (w, w)
__constant__ ulonglong2 c_wb4[A_D * H_ / 2];  // [a*4 + h2]: .x=head 2h2, .y=head 2h2+1

__device__ __forceinline__ u64 pack2(float x, float y) {
    u64 r; asm("mov.b64 %0, {%1, %2};" : "=l"(r) : "f"(x), "f"(y)); return r;
}
__device__ __forceinline__ void unpack2(u64 v, float& x, float& y) {
    asm("mov.b64 {%0, %1}, %2;" : "=f"(x), "=f"(y) : "l"(v));
}
__device__ __forceinline__ u64 fma2(u64 a, u64 b, u64 c) {
    u64 d; asm("fma.rn.f32x2 %0, %1, %2, %3;" : "=l"(d) : "l"(a), "l"(b), "l"(c)); return d;
}
__device__ __forceinline__ u64 add2(u64 a, u64 b) {
    u64 d; asm("add.rn.f32x2 %0, %1, %2;" : "=l"(d) : "l"(a), "l"(b)); return d;
}
__device__ __forceinline__ float tanh_ap(float x) {
    float y; asm("tanh.approx.f32 %0, %1;" : "=f"(y) : "f"(x)); return y;
}
__device__ __forceinline__ u64 tanh2(u64 v) {
    float x, y; unpack2(v, x, y);
    return pack2(tanh_ap(x), tanh_ap(y));
}

// ---------------------------------------------------------------------------
// Kernel W: duplicate Wb scalars into (w,w) pairs for f32x2 FMAs.
// ---------------------------------------------------------------------------
__global__ void kW(const float* __restrict__ Wb)
{
    int i = blockIdx.x * 256 + threadIdx.x;
    if (i < A_D * H_) {
        float v = Wb[i];
        g_wbDup[i] = pack2(v, v);
    }
}

// ---------------------------------------------------------------------------
// Kernel A: proj = emb_gene[omc] @ W0 + b0, scattered into gene-paired layout.
// ---------------------------------------------------------------------------
__global__ __launch_bounds__(128) void kA(
    const int* __restrict__ omc, const float* __restrict__ eg,
    const float* __restrict__ W0, const float* __restrict__ b0)
{
    __shared__ float EsT[E_D * 8];   // [e][r]
    __shared__ int idxs[8];
    const int R0 = blockIdx.x * 8;
    const int b  = R0 / N_;
    const int nb = R0 - b * N_;
    const int t  = threadIdx.x;

    if (t < 8) idxs[t] = omc[R0 + t];
    __syncthreads();
    for (int i = t; i < 8 * E_D; i += 128) {
        int r = i / E_D, e = i - r * E_D;
        EsT[e * 8 + r] = eg[(long)idxs[r] * E_D + e];
    }
    __syncthreads();

    const int k  = t & 63;           // a-pair: a = 2k, 2k+1
    const int rg = t >> 6;           // row group (4 rows each)
    const u64* W2 = (const u64*)W0;  // [e][64] pairs
    const u64  bias = ((const u64*)b0)[k];

    u64 acc[4];
#pragma unroll
    for (int r = 0; r < 4; r++) acc[r] = bias;

#pragma unroll 4
    for (int e = 0; e < E_D; e++) {
        u64 w = W2[e * 64 + k];
        const float* er = EsT + e * 8 + rg * 4;
        acc[0] = fma2(pack2(er[0], er[0]), w, acc[0]);
        acc[1] = fma2(pack2(er[1], er[1]), w, acc[1]);
        acc[2] = fma2(pack2(er[2], er[2]), w, acc[2]);
        acc[3] = fma2(pack2(er[3], er[3]), w, acc[3]);
    }

    float* pf = (float*)g_projP;
#pragma unroll
    for (int r = 0; r < 4; r++) {
        const int n = nb + rg * 4 + r;          // gene index within batch b
        const int chunk = n >> 6;
        const int idx   = n & 63;
        int lane, comp;
        if (chunk < 6) { lane = idx & 31; comp = idx >> 5; }
        else           { lane = idx & 7;  comp = idx >> 3; }
        // float layout of ulonglong2 cell: {aLo.gLo, aLo.gHi, aHi.gLo, aHi.gHi}
        const int fbase = (((b * NCH + chunk) * 64 + k) * 32 + lane) * 4 + comp;
        float x, y;
        unpack2(acc[r], x, y);
        pf[fbase]     = x;      // a = 2k
        pf[fbase + 2] = y;      // a = 2k+1
    }
}

// ---------------------------------------------------------------------------
// Kernel B (scores + softmax) — R15 port-balanced version, unchanged.
//
// SMEM floats:
//   sc    [0, 12800)       scores PT*H*N
//   epsQ  [12800, 13824)   2 groups x 128 a x {dupA u64, dupB u64}
//   wbS   [13824, 14848)   128 a x heads 4..7 dup pairs
//   sinv  [14848, 14880)
//   bbs   [14880, 14888)
// = 59552 bytes -> 3 blocks/SM
// ---------------------------------------------------------------------------
#define SMEM_B_FLOATS 14888
#define SMEM_B_BYTES  (SMEM_B_FLOATS * 4)

extern __shared__ float smemB[];

#define STAGE_FMA(wc, wbB, T0, T1, T2, T3)                              \
    do {                                                                \
        ulonglong2 wA = c_wb4[(wc) + 0];                                \
        accA[0] = fma2(T0, wA.x, accA[0]);                              \
        accB[0] = fma2(T1, wA.x, accB[0]);                              \
        accA[1] = fma2(T0, wA.y, accA[1]);                              \
        accB[1] = fma2(T1, wA.y, accB[1]);                              \
        ulonglong2 wB = c_wb4[(wc) + 1];                                \
        accA[2] = fma2(T0, wB.x, accA[2]);                              \
        accB[2] = fma2(T1, wB.x, accB[2]);                              \
        accA[3] = fma2(T0, wB.y, accA[3]);                              \
        accB[3] = fma2(T1, wB.y, accB[3]);                              \
        ulonglong2 wC = *(const ulonglong2*)(wbB);                      \
        accA[4] = fma2(T0, wC.x, accA[4]);                              \
        accB[4] = fma2(T1, wC.x, accB[4]);                              \
        accA[5] = fma2(T0, wC.y, accA[5]);                              \
        accB[5] = fma2(T1, wC.y, accB[5]);                              \
        ulonglong2 wD = *(const ulonglong2*)((wbB) + 16);               \
        accA[6] = fma2(T0, wD.x, accA[6]);                              \
        accB[6] = fma2(T1, wD.x, accB[6]);                              \
        accA[7] = fma2(T0, wD.y, accA[7]);                              \
        accB[7] = fma2(T1, wD.y, accB[7]);                              \
        ulonglong2 wE = c_wb4[(wc) + 4];                                \
        accA[0] = fma2(T2, wE.x, accA[0]);                              \
        accB[0] = fma2(T3, wE.x, accB[0]);                              \
        accA[1] = fma2(T2, wE.y, accA[1]);                              \
        accB[1] = fma2(T3, wE.y, accB[1]);                              \
        ulonglong2 wF = c_wb4[(wc) + 5];                                \
        accA[2] = fma2(T2, wF.x, accA[2]);                              \
        accB[2] = fma2(T3, wF.x, accB[2]);                              \
        accA[3] = fma2(T2, wF.y, accA[3]);                              \
        accB[3] = fma2(T3, wF.y, accB[3]);                              \
        ulonglong2 wG = *(const ulonglong2*)((wbB) + 32);               \
        accA[4] = fma2(T2, wG.x, accA[4]);                              \
        accB[4] = fma2(T3, wG.x, accB[4]);                              \
        accA[5] = fma2(T2, wG.y, accA[5]);                              \
        accB[5] = fma2(T3, wG.y, accB[5]);                              \
        ulonglong2 wH = *(const ulonglong2*)((wbB) + 48);               \
        accA[6] = fma2(T2, wH.x, accA[6]);                              \
        accB[6] = fma2(T3, wH.x, accB[6]);                              \
        accA[7] = fma2(T2, wH.y, accA[7]);                              \
        accB[7] = fma2(T3, wH.y, accB[7]);                              \
    } while (0)

#define STAGE_TANH(L, epB, D0, D1, D2, D3)                              \
    do {                                                                \
        ulonglong2 e0 = *(const ulonglong2*)(epB);                      \
        D0 = tanh2(add2((L).x, e0.x));                                  \
        D1 = tanh2(add2((L).x, e0.y));                                  \
        ulonglong2 e1 = *(const ulonglong2*)((epB) + 16);               \
        D2 = tanh2(add2((L).y, e1.x));                                  \
        D3 = tanh2(add2((L).y, e1.y));                                  \
    } while (0)

__global__ __launch_bounds__(256, 3) void kB(
    const int* __restrict__ ptw, const float* __restrict__ ept,
    const float* __restrict__ Wb, const float* __restrict__ bb)
{
    float* sc   = smemB;
    ulonglong2* epsQ = (ulonglong2*)(smemB + 12800);  // [group*128 + a]
    u64*   wbS  = (u64*)(smemB + 13824);              // [a*4 + (h-4)]
    float* sinv = smemB + 14848;
    float* bbs  = smemB + 14880;

    const int bx   = blockIdx.x;
    const int b    = bx / 50;
    const int pt   = bx - b * 50;
    const int t    = threadIdx.x;
    const int w    = t >> 5;
    const int lane = t & 31;

    {
        float* ef = (float*)epsQ;
        for (int i = t; i < 1024; i += 256) {
            int g  = i >> 9;
            int a  = (i >> 2) & 127;
            int c4 = i & 3;
            int pl = g * 2 + (c4 >> 1);
            ef[(g * 128 + a) * 4 + c4] = ept[(long)ptw[pt * PT + pl] * A_D + a];
        }
    }
    for (int i = t; i < 512; i += 256) {
        int a = i >> 2, j = i & 3;
        float v = Wb[a * H_ + 4 + j];
        wbS[i] = pack2(v, v);
    }
    if (t < 8) bbs[t] = bb[t];
    __syncthreads();

    {
        const int pairI = w & 1;
        float* scA = sc + (2 * pairI + 0) * H_ * N_;
        float* scB = sc + (2 * pairI + 1) * H_ * N_;
        const char* epBase = (const char*)(epsQ + pairI * 128);
        const char* wbBase = (const char*)wbS;

        for (int c = w >> 1; c < NCH; c += 4) {
            u64 accA[H_], accB[H_];
#pragma unroll
            for (int h = 0; h < H_; h++) { accA[h] = 0ull; accB[h] = 0ull; }

            const char* ppB = (const char*)(g_projP + ((b * NCH + c) * 64) * 32 + lane);
            const char* epB = epBase;
            const char* wbB = wbBase;

            u64 T0, T1, T2, T3, U0, U1, U2, U3;
            {
                ulonglong2 L0 = *(const ulonglong2*)ppB;
                STAGE_TANH(L0, epB, T0, T1, T2, T3);
            }
            ulonglong2 L1 = *(const ulonglong2*)(ppB + 512);
            ulonglong2 L2 = *(const ulonglong2*)(ppB + 1024);
            ppB += 1536;
            epB += 32;

            int wc = 0;
#pragma unroll 2
            for (int s = 0; s < 62; s++) {
                STAGE_TANH(L1, epB, U0, U1, U2, U3);     // tanh for s+1
                STAGE_FMA(wc, wbB, T0, T1, T2, T3);      // FMA  for s
                L1 = L2;
                L2 = *(const ulonglong2*)ppB;            // load s+3
                T0 = U0; T1 = U1; T2 = U2; T3 = U3;
                ppB += 512;
                epB += 32;
                wc += 8;
                wbB += 64;
            }
            STAGE_TANH(L1, epB, U0, U1, U2, U3);
            STAGE_FMA(wc, wbB, T0, T1, T2, T3);
            STAGE_FMA(wc + 8, wbB + 64, U0, U1, U2, U3);

            int geneA, geneB;
            bool valid;
            if (c < 6) { geneA = c * 64 + lane; geneB = geneA + 32; valid = true; }
            else       { geneA = 384 + (lane & 7); geneB = geneA + 8; valid = (lane < 8); }
            if (valid) {
#pragma unroll
                for (int h = 0; h < H_; h++) {
                    float xA, yA, xB, yB;
                    unpack2(accA[h], xA, yA);
                    unpack2(accB[h], xB, yB);
                    const float bh = bbs[h];
                    scA[h * N_ + geneA] = xA + bh;
                    scA[h * N_ + geneB] = yA + bh;
                    scB[h * N_ + geneA] = xB + bh;
                    scB[h * N_ + geneB] = yB + bh;
                }
            }
        }
    }
    __syncthreads();

    const int p    = w >> 1;
    const int half = w & 1;
    const int pg   = pt * PT + p;
    float* scp = sc + p * H_ * N_;
#pragma unroll
    for (int q = 0; q < 4; q++) {
        const int h = half * 4 + q;
        float* row = scp + h * N_;
        float m = -1e30f;
        for (int i = lane; i < N_; i += 32) m = fmaxf(m, row[i]);
#pragma unroll
        for (int o = 16; o; o >>= 1) m = fmaxf(m, __shfl_xor_sync(0xffffffffu, m, o));
        float s = 0.f;
        for (int i = lane; i < N_; i += 32) {
            float e = __expf(row[i] - m);
            row[i] = e;
            s += e;
        }
#pragma unroll
        for (int o = 16; o; o >>= 1) s += __shfl_xor_sync(0xffffffffu, s, o);
        if (lane == 0) sinv[p * H_ + h] = __fdividef(1.f, s);
    }
    __syncthreads();

    {
        float iv[H_];
#pragma unroll
        for (int h = 0; h < H_; h++) iv[h] = sinv[p * H_ + h];
        float* gap = g_attn + ((long)(b * P_) + pg) * N_;
        for (int i = lane; i < 200; i += 32) {
            const int n = half * 200 + i;
            float a = 0.f;
#pragma unroll
            for (int h = 0; h < H_; h++) a = fmaf(scp[h * N_ + n], iv[h], a);
            gap[n] = a;
        }
    }
}

// ---------------------------------------------------------------------------
// Kernel C (pooling, v4): double-buffered 32-gene chunks, ALL compile-time
// trip counts (no local arrays, no min()). 12 full chunks + unrolled 16-gene
// tail. One barrier per chunk. Warp = (quad q, gene-quarter gq); per gene one
// E-row read feeds 4 pathways (v2 reuse layout).
//
// SMEM floats:
//   buf0  [0, 6400)        32 genes x 200
//   buf1  [6400, 12800)    32 genes x 200
//   attnS [12800, 16000)   8 x 400
// = 64000 bytes -> 3 blocks/SM (reg-limited at 3 anyway)
// ---------------------------------------------------------------------------
#define SMEM_C_FLOATS 16000
#define SMEM_C_BYTES  (SMEM_C_FLOATS * 4)

// copy one 200-float E row (50 u128): lanes 0-31 + tail 18
#define COPY_ROW(dst, src)                                              \
    do {                                                                \
        (dst)[lane] = (src)[lane];                                      \
        if (lane < 18) (dst)[32 + lane] = (src)[32 + lane];             \
    } while (0)

// accumulate one gene n (row in cur, attn index na)
#define POOL_GENE(cur, n, na)                                           \
    do {                                                                \
        float f0 = ap0[na], f1 = ap1[na], f2 = ap2[na], f3 = ap3[na];   \
        u64 v0 = pack2(f0, f0);                                         \
        u64 v1 = pack2(f1, f1);                                         \
        u64 v2 = pack2(f2, f2);                                         \
        u64 v3 = pack2(f3, f3);                                         \
        ulonglong2 e0 = (cur)[(n) * 50 + lane];                         \
        a00 = fma2(e0.x, v0, a00);  a01 = fma2(e0.y, v0, a01);          \
        a10 = fma2(e0.x, v1, a10);  a11 = fma2(e0.y, v1, a11);          \
        a20 = fma2(e0.x, v2, a20);  a21 = fma2(e0.y, v2, a21);          \
        a30 = fma2(e0.x, v3, a30);  a31 = fma2(e0.y, v3, a31);          \
        if (lane < 18) {                                                \
            ulonglong2 e1 = (cur)[(n) * 50 + 32 + lane];                \
            a02 = fma2(e1.x, v0, a02);  a03 = fma2(e1.y, v0, a03);      \
            a12 = fma2(e1.x, v1, a12);  a13 = fma2(e1.y, v1, a13);      \
            a22 = fma2(e1.x, v2, a22);  a23 = fma2(e1.y, v2, a23);      \
            a32 = fma2(e1.x, v3, a32);  a33 = fma2(e1.y, v3, a33);      \
        }                                                               \
    } while (0)

__global__ __launch_bounds__(256, 3) void kC(
    const int* __restrict__ omc, const float* __restrict__ eg,
    float* __restrict__ out)
{
    float* attnS = smemB + 12800;

    const int bx   = blockIdx.x;
    const int b    = bx / 25;
    const int pt8  = bx - b * 25;       // pathway octet
    const int t    = threadIdx.x;
    const int w    = t >> 5;
    const int lane = t & 31;
    const int q    = w >> 2;            // pathway quad 0..1
    const int gq   = w & 3;             // gene quarter

    const ulonglong2* egq = (const ulonglong2*)eg;   // 50 u128 per vocab row
    ulonglong2* buf0 = (ulonglong2*)smemB;           // 1600 u128
    ulonglong2* buf1 = (ulonglong2*)(smemB + 6400);
    const int* omcb = omc + b * N_;

    // stage attn for 8 pathways (3200 floats)
    {
        const float4* gA0 = (const float4*)(g_attn + ((long)(b * P_) + pt8 * 8) * N_);
        float4* aS = (float4*)attnS;
        for (int i = t; i < 800; i += 256) aS[i] = gA0[i];
    }

    // stage chunk 0: rows w, w+8, w+16, w+24 — fully unrolled scalars
    {
        int i0 = omcb[w];
        int i1 = omcb[w + 8];
        int i2 = omcb[w + 16];
        int i3 = omcb[w + 24];
        COPY_ROW(buf0 + w * 50,        egq + (long)i0 * 50);
        COPY_ROW(buf0 + (w + 8) * 50,  egq + (long)i1 * 50);
        COPY_ROW(buf0 + (w + 16) * 50, egq + (long)i2 * 50);
        COPY_ROW(buf0 + (w + 24) * 50, egq + (long)i3 * 50);
    }
    __syncthreads();

    const float* ap0 = attnS + (q * 4 + 0) * N_;
    const float* ap1 = attnS + (q * 4 + 1) * N_;
    const float* ap2 = attnS + (q * 4 + 2) * N_;
    const float* ap3 = attnS + (q * 4 + 3) * N_;

    u64 a00=0, a01=0, a02=0, a03=0;
    u64 a10=0, a11=0, a12=0, a13=0;
    u64 a20=0, a21=0, a22=0, a23=0;
    u64 a30=0, a31=0, a32=0, a33=0;

#pragma unroll 1
    for (int c = 0; c < 12; c++) {
        ulonglong2* cur = (c & 1) ? buf1 : buf0;
        ulonglong2* nxt = (c & 1) ? buf0 : buf1;
        const int n0 = c * 32;

        // stage next chunk (overlaps with compute below)
        if (c < 11) {
            const int nn0 = n0 + 32;
            int i0 = omcb[nn0 + w];
            int i1 = omcb[nn0 + w + 8];
            int i2 = omcb[nn0 + w + 16];
            int i3 = omcb[nn0 + w + 24];
            COPY_ROW(nxt + w * 50,        egq + (long)i0 * 50);
            COPY_ROW(nxt + (w + 8) * 50,  egq + (long)i1 * 50);
            COPY_ROW(nxt + (w + 16) * 50, egq + (long)i2 * 50);
            COPY_ROW(nxt + (w + 24) * 50, egq + (long)i3 * 50);
        } else {
            // stage tail (genes 384..399, 16 rows): rows w, w+8
            int i0 = omcb[384 + w];
            int i1 = omcb[384 + w + 8];
            COPY_ROW(nxt + w * 50,       egq + (long)i0 * 50);
            COPY_ROW(nxt + (w + 8) * 50, egq + (long)i1 * 50);
        }

        // compute chunk c: genes gq + 4j, j = 0..7 (fully unrolled)
#pragma unroll
        for (int j = 0; j < 8; j++) {
            const int n = gq + 4 * j;
            POOL_GENE(cur, n, n0 + n);
        }
        __syncthreads();
    }
    // tail chunk (16 genes) in buf0 (12 & 1 == 0)
#pragma unroll
    for (int j = 0; j < 4; j++) {
        const int n = gq + 4 * j;
        POOL_GENE(buf0, n, 384 + n);
    }
    __syncthreads();   // buf regions free; reuse for reduction

    // reduction over gene-quarters via smem.
    // red layout: [(q*3 + (gq-1))*4 + p] rows of 50 u128 -> 24 x 50 u128
    ulonglong2* red = buf0;
    if (gq != 0) {
        ulonglong2* r0 = red + ((q * 3 + (gq - 1)) * 4 + 0) * 50;
        ulonglong2* r1 = red + ((q * 3 + (gq - 1)) * 4 + 1) * 50;
        ulonglong2* r2 = red + ((q * 3 + (gq - 1)) * 4 + 2) * 50;
        ulonglong2* r3 = red + ((q * 3 + (gq - 1)) * 4 + 3) * 50;
        ulonglong2 s;
        s.x = a00; s.y = a01; r0[lane] = s;
        s.x = a10; s.y = a11; r1[lane] = s;
        s.x = a20; s.y = a21; r2[lane] = s;
        s.x = a30; s.y = a31; r3[lane] = s;
        if (lane < 18) {
            s.x = a02; s.y = a03; r0[32 + lane] = s;
            s.x = a12; s.y = a13; r1[32 + lane] = s;
            s.x = a22; s.y = a23; r2[32 + lane] = s;
            s.x = a32; s.y = a33; r3[32 + lane] = s;
        }
    }
    __syncthreads();
    if (gq == 0) {
#pragma unroll
        for (int j = 0; j < 3; j++) {
            const ulonglong2* r0 = red + ((q * 3 + j) * 4 + 0) * 50;
            const ulonglong2* r1 = red + ((q * 3 + j) * 4 + 1) * 50;
            const ulonglong2* r2 = red + ((q * 3 + j) * 4 + 2) * 50;
            const ulonglong2* r3 = red + ((q * 3 + j) * 4 + 3) * 50;
            ulonglong2 s;
            s = r0[lane]; a00 = add2(a00, s.x); a01 = add2(a01, s.y);
            s = r1[lane]; a10 = add2(a10, s.x); a11 = add2(a11, s.y);
            s = r2[lane]; a20 = add2(a20, s.x); a21 = add2(a21, s.y);
            s = r3[lane]; a30 = add2(a30, s.x); a31 = add2(a31, s.y);
            if (lane < 18) {
                s = r0[32 + lane]; a02 = add2(a02, s.x); a03 = add2(a03, s.y);
                s = r1[32 + lane]; a12 = add2(a12, s.x); a13 = add2(a13, s.y);
                s = r2[32 + lane]; a22 = add2(a22, s.x); a23 = add2(a23, s.y);
                s = r3[32 + lane]; a32 = add2(a32, s.x); a33 = add2(a33, s.y);
            }
        }
        const int pg0 = pt8 * 8 + q * 4;
        ulonglong2* op0 = (ulonglong2*)(out + (long)(b * P_ + pg0 + 0) * E_D);
        ulonglong2* op1 = (ulonglong2*)(out + (long)(b * P_ + pg0 + 1) * E_D);
        ulonglong2* op2 = (ulonglong2*)(out + (long)(b * P_ + pg0 + 2) * E_D);
        ulonglong2* op3 = (ulonglong2*)(out + (long)(b * P_ + pg0 + 3) * E_D);
        ulonglong2 s;
        s.x = a00; s.y = a01; op0[lane] = s;
        s.x = a10; s.y = a11; op1[lane] = s;
        s.x = a20; s.y = a21; op2[lane] = s;
        s.x = a30; s.y = a31; op3[lane] = s;
        if (lane < 18) {
            s.x = a02; s.y = a03; op0[32 + lane] = s;
            s.x = a12; s.y = a13; op1[32 + lane] = s;
            s.x = a22; s.y = a23; op2[32 + lane] = s;
            s.x = a32; s.y = a33; op3[32 + lane] = s;
        }
    }
}

// ---------------------------------------------------------------------------
extern "C" void kernel_launch(void* const* d_in, const int* in_sizes, int n_in,
                              void* d_out, int out_size)
{
    const int*   omc = (const int*)  d_in[0];
    const int*   ptw = (const int*)  d_in[1];
    const float* eg  = (const float*)d_in[2];
    const float* ept = (const float*)d_in[3];
    const float* W0  = (const float*)d_in[4];
    const float* b0  = (const float*)d_in[5];
    const float* Wb  = (const float*)d_in[6];
    const float* bb  = (const float*)d_in[7];
    float* out = (float*)d_out;

    kW<<<4, 256>>>(Wb);
    void* srcp = nullptr;
    cudaGetSymbolAddress(&srcp, g_wbDup);
    void* dstp = nullptr;
    cudaGetSymbolAddress(&dstp, c_wb4);
    cudaMemcpyAsync(dstp, srcp, sizeof(u64) * A_D * H_,
                    cudaMemcpyDeviceToDevice, 0);

    kA<<<(B_ * N_) / 8, 128>>>(omc, eg, W0, b0);

    cudaFuncSetAttribute(kB, cudaFuncAttributeMaxDynamicSharedMemorySize,
                         SMEM_B_BYTES);
    kB<<<B_ * (P_ / PT), 256, SMEM_B_BYTES>>>(ptw, ept, Wb, bb);

    cudaFuncSetAttribute(kC, cudaFuncAttributeMaxDynamicSharedMemorySize,
                         SMEM_C_BYTES);
    kC<<<B_ * (P_ / 8), 256, SMEM_C_BYTES>>>(omc, eg, out);
}

// round 17
// speedup vs baseline: 1.1042x; 1.0107x over previous
#include <cuda_runtime.h>

#define B_    16
#define N_    400
#define P_    200
#define E_D   200
#define A_D   128
#define H_    8
#define PT    4      // pathways per block in kernel B
#define NCH   7      // gene chunks of 64 for kA/kB layout

typedef unsigned long long u64;

// proj scratch: ulonglong2 at ((b*NCH + c)*64 + k)*32 + lane =
//   { u64(prj[gLo][2k],  prj[gHi][2k]),  u64(prj[gLo][2k+1], prj[gHi][2k+1]) }
// gLo = c*64+lane, gHi = gLo+32 (c<6); chunk 6: lane<8, gLo=384+lane, gHi=gLo+8.
__device__ ulonglong2 g_projP[B_ * NCH * 64 * 32];

// attn scratch (B, P, N) written by kB phase 2, consumed by kC.
__device__ float g_attn[B_ * P_ * N_];

// Wb duplicated pairs: staging (device) -> constant (heads 0-3 used there).
__device__ u64 g_wbDup[A_D * H_];             // [a*8 + h] = (w, w)
__constant__ ulonglong2 c_wb4[A_D * H_ / 2];  // [a*4 + h2]: .x=head 2h2, .y=head 2h2+1

__device__ __forceinline__ u64 pack2(float x, float y) {
    u64 r; asm("mov.b64 %0, {%1, %2};" : "=l"(r) : "f"(x), "f"(y)); return r;
}
__device__ __forceinline__ void unpack2(u64 v, float& x, float& y) {
    asm("mov.b64 {%0, %1}, %2;" : "=f"(x), "=f"(y) : "l"(v));
}
__device__ __forceinline__ u64 fma2(u64 a, u64 b, u64 c) {
    u64 d; asm("fma.rn.f32x2 %0, %1, %2, %3;" : "=l"(d) : "l"(a), "l"(b), "l"(c)); return d;
}
__device__ __forceinline__ u64 add2(u64 a, u64 b) {
    u64 d; asm("add.rn.f32x2 %0, %1, %2;" : "=l"(d) : "l"(a), "l"(b)); return d;
}
__device__ __forceinline__ float tanh_ap(float x) {
    float y; asm("tanh.approx.f32 %0, %1;" : "=f"(y) : "f"(x)); return y;
}
__device__ __forceinline__ u64 tanh2(u64 v) {
    float x, y; unpack2(v, x, y);
    return pack2(tanh_ap(x), tanh_ap(y));
}

// ---------------------------------------------------------------------------
// Kernel W: duplicate Wb scalars into (w,w) pairs for f32x2 FMAs.
// ---------------------------------------------------------------------------
__global__ void kW(const float* __restrict__ Wb)
{
    int i = blockIdx.x * 256 + threadIdx.x;
    if (i < A_D * H_) {
        float v = Wb[i];
        g_wbDup[i] = pack2(v, v);
    }
}

// ---------------------------------------------------------------------------
// Kernel A: proj = emb_gene[omc] @ W0 + b0, scattered into gene-paired layout.
// ---------------------------------------------------------------------------
__global__ __launch_bounds__(128) void kA(
    const int* __restrict__ omc, const float* __restrict__ eg,
    const float* __restrict__ W0, const float* __restrict__ b0)
{
    __shared__ float EsT[E_D * 8];   // [e][r]
    __shared__ int idxs[8];
    const int R0 = blockIdx.x * 8;
    const int b  = R0 / N_;
    const int nb = R0 - b * N_;
    const int t  = threadIdx.x;

    if (t < 8) idxs[t] = omc[R0 + t];
    __syncthreads();
    for (int i = t; i < 8 * E_D; i += 128) {
        int r = i / E_D, e = i - r * E_D;
        EsT[e * 8 + r] = eg[(long)idxs[r] * E_D + e];
    }
    __syncthreads();

    const int k  = t & 63;           // a-pair: a = 2k, 2k+1
    const int rg = t >> 6;           // row group (4 rows each)
    const u64* W2 = (const u64*)W0;  // [e][64] pairs
    const u64  bias = ((const u64*)b0)[k];

    u64 acc[4];
#pragma unroll
    for (int r = 0; r < 4; r++) acc[r] = bias;

#pragma unroll 4
    for (int e = 0; e < E_D; e++) {
        u64 w = W2[e * 64 + k];
        const float* er = EsT + e * 8 + rg * 4;
        acc[0] = fma2(pack2(er[0], er[0]), w, acc[0]);
        acc[1] = fma2(pack2(er[1], er[1]), w, acc[1]);
        acc[2] = fma2(pack2(er[2], er[2]), w, acc[2]);
        acc[3] = fma2(pack2(er[3], er[3]), w, acc[3]);
    }

    float* pf = (float*)g_projP;
#pragma unroll
    for (int r = 0; r < 4; r++) {
        const int n = nb + rg * 4 + r;          // gene index within batch b
        const int chunk = n >> 6;
        const int idx   = n & 63;
        int lane, comp;
        if (chunk < 6) { lane = idx & 31; comp = idx >> 5; }
        else           { lane = idx & 7;  comp = idx >> 3; }
        // float layout of ulonglong2 cell: {aLo.gLo, aLo.gHi, aHi.gLo, aHi.gHi}
        const int fbase = (((b * NCH + chunk) * 64 + k) * 32 + lane) * 4 + comp;
        float x, y;
        unpack2(acc[r], x, y);
        pf[fbase]     = x;      // a = 2k
        pf[fbase + 2] = y;      // a = 2k+1
    }
}

// ---------------------------------------------------------------------------
// Kernel B (scores + softmax) — R15/R16 port-balanced version, unchanged.
//
// SMEM floats:
//   sc    [0, 12800)       scores PT*H*N
//   epsQ  [12800, 13824)   2 groups x 128 a x {dupA u64, dupB u64}
//   wbS   [13824, 14848)   128 a x heads 4..7 dup pairs
//   sinv  [14848, 14880)
//   bbs   [14880, 14888)
// = 59552 bytes -> 3 blocks/SM
// ---------------------------------------------------------------------------
#define SMEM_B_FLOATS 14888
#define SMEM_B_BYTES  (SMEM_B_FLOATS * 4)

extern __shared__ float smemB[];

#define STAGE_FMA(wc, wbB, T0, T1, T2, T3)                              \
    do {                                                                \
        ulonglong2 wA = c_wb4[(wc) + 0];                                \
        accA[0] = fma2(T0, wA.x, accA[0]);                              \
        accB[0] = fma2(T1, wA.x, accB[0]);                              \
        accA[1] = fma2(T0, wA.y, accA[1]);                              \
        accB[1] = fma2(T1, wA.y, accB[1]);                              \
        ulonglong2 wB = c_wb4[(wc) + 1];                                \
        accA[2] = fma2(T0, wB.x, accA[2]);                              \
        accB[2] = fma2(T1, wB.x, accB[2]);                              \
        accA[3] = fma2(T0, wB.y, accA[3]);                              \
        accB[3] = fma2(T1, wB.y, accB[3]);                              \
        ulonglong2 wC = *(const ulonglong2*)(wbB);                      \
        accA[4] = fma2(T0, wC.x, accA[4]);                              \
        accB[4] = fma2(T1, wC.x, accB[4]);                              \
        accA[5] = fma2(T0, wC.y, accA[5]);                              \
        accB[5] = fma2(T1, wC.y, accB[5]);                              \
        ulonglong2 wD = *(const ulonglong2*)((wbB) + 16);               \
        accA[6] = fma2(T0, wD.x, accA[6]);                              \
        accB[6] = fma2(T1, wD.x, accB[6]);                              \
        accA[7] = fma2(T0, wD.y, accA[7]);                              \
        accB[7] = fma2(T1, wD.y, accB[7]);                              \
        ulonglong2 wE = c_wb4[(wc) + 4];                                \
        accA[0] = fma2(T2, wE.x, accA[0]);                              \
        accB[0] = fma2(T3, wE.x, accB[0]);                              \
        accA[1] = fma2(T2, wE.y, accA[1]);                              \
        accB[1] = fma2(T3, wE.y, accB[1]);                              \
        ulonglong2 wF = c_wb4[(wc) + 5];                                \
        accA[2] = fma2(T2, wF.x, accA[2]);                              \
        accB[2] = fma2(T3, wF.x, accB[2]);                              \
        accA[3] = fma2(T2, wF.y, accA[3]);                              \
        accB[3] = fma2(T3, wF.y, accB[3]);                              \
        ulonglong2 wG = *(const ulonglong2*)((wbB) + 32);               \
        accA[4] = fma2(T2, wG.x, accA[4]);                              \
        accB[4] = fma2(T3, wG.x, accB[4]);                              \
        accA[5] = fma2(T2, wG.y, accA[5]);                              \
        accB[5] = fma2(T3, wG.y, accB[5]);                              \
        ulonglong2 wH = *(const ulonglong2*)((wbB) + 48);               \
        accA[6] = fma2(T2, wH.x, accA[6]);                              \
        accB[6] = fma2(T3, wH.x, accB[6]);                              \
        accA[7] = fma2(T2, wH.y, accA[7]);                              \
        accB[7] = fma2(T3, wH.y, accB[7]);                              \
    } while (0)

#define STAGE_TANH(L, epB, D0, D1, D2, D3)                              \
    do {                                                                \
        ulonglong2 e0 = *(const ulonglong2*)(epB);                      \
        D0 = tanh2(add2((L).x, e0.x));                                  \
        D1 = tanh2(add2((L).x, e0.y));                                  \
        ulonglong2 e1 = *(const ulonglong2*)((epB) + 16);               \
        D2 = tanh2(add2((L).y, e1.x));                                  \
        D3 = tanh2(add2((L).y, e1.y));                                  \
    } while (0)

__global__ __launch_bounds__(256, 3) void kB(
    const int* __restrict__ ptw, const float* __restrict__ ept,
    const float* __restrict__ Wb, const float* __restrict__ bb)
{
    float* sc   = smemB;
    ulonglong2* epsQ = (ulonglong2*)(smemB + 12800);  // [group*128 + a]
    u64*   wbS  = (u64*)(smemB + 13824);              // [a*4 + (h-4)]
    float* sinv = smemB + 14848;
    float* bbs  = smemB + 14880;

    const int bx   = blockIdx.x;
    const int b    = bx / 50;
    const int pt   = bx - b * 50;
    const int t    = threadIdx.x;
    const int w    = t >> 5;
    const int lane = t & 31;

    {
        float* ef = (float*)epsQ;
        for (int i = t; i < 1024; i += 256) {
            int g  = i >> 9;
            int a  = (i >> 2) & 127;
            int c4 = i & 3;
            int pl = g * 2 + (c4 >> 1);
            ef[(g * 128 + a) * 4 + c4] = ept[(long)ptw[pt * PT + pl] * A_D + a];
        }
    }
    for (int i = t; i < 512; i += 256) {
        int a = i >> 2, j = i & 3;
        float v = Wb[a * H_ + 4 + j];
        wbS[i] = pack2(v, v);
    }
    if (t < 8) bbs[t] = bb[t];
    __syncthreads();

    {
        const int pairI = w & 1;
        float* scA = sc + (2 * pairI + 0) * H_ * N_;
        float* scB = sc + (2 * pairI + 1) * H_ * N_;
        const char* epBase = (const char*)(epsQ + pairI * 128);
        const char* wbBase = (const char*)wbS;

        for (int c = w >> 1; c < NCH; c += 4) {
            u64 accA[H_], accB[H_];
#pragma unroll
            for (int h = 0; h < H_; h++) { accA[h] = 0ull; accB[h] = 0ull; }

            const char* ppB = (const char*)(g_projP + ((b * NCH + c) * 64) * 32 + lane);
            const char* epB = epBase;
            const char* wbB = wbBase;

            u64 T0, T1, T2, T3, U0, U1, U2, U3;
            {
                ulonglong2 L0 = *(const ulonglong2*)ppB;
                STAGE_TANH(L0, epB, T0, T1, T2, T3);
            }
            ulonglong2 L1 = *(const ulonglong2*)(ppB + 512);
            ulonglong2 L2 = *(const ulonglong2*)(ppB + 1024);
            ppB += 1536;
            epB += 32;

            int wc = 0;
#pragma unroll 2
            for (int s = 0; s < 62; s++) {
                STAGE_TANH(L1, epB, U0, U1, U2, U3);     // tanh for s+1
                STAGE_FMA(wc, wbB, T0, T1, T2, T3);      // FMA  for s
                L1 = L2;
                L2 = *(const ulonglong2*)ppB;            // load s+3
                T0 = U0; T1 = U1; T2 = U2; T3 = U3;
                ppB += 512;
                epB += 32;
                wc += 8;
                wbB += 64;
            }
            STAGE_TANH(L1, epB, U0, U1, U2, U3);
            STAGE_FMA(wc, wbB, T0, T1, T2, T3);
            STAGE_FMA(wc + 8, wbB + 64, U0, U1, U2, U3);

            int geneA, geneB;
            bool valid;
            if (c < 6) { geneA = c * 64 + lane; geneB = geneA + 32; valid = true; }
            else       { geneA = 384 + (lane & 7); geneB = geneA + 8; valid = (lane < 8); }
            if (valid) {
#pragma unroll
                for (int h = 0; h < H_; h++) {
                    float xA, yA, xB, yB;
                    unpack2(accA[h], xA, yA);
                    unpack2(accB[h], xB, yB);
                    const float bh = bbs[h];
                    scA[h * N_ + geneA] = xA + bh;
                    scA[h * N_ + geneB] = yA + bh;
                    scB[h * N_ + geneA] = xB + bh;
                    scB[h * N_ + geneB] = yB + bh;
                }
            }
        }
    }
    __syncthreads();

    const int p    = w >> 1;
    const int half = w & 1;
    const int pg   = pt * PT + p;
    float* scp = sc + p * H_ * N_;
#pragma unroll
    for (int q = 0; q < 4; q++) {
        const int h = half * 4 + q;
        float* row = scp + h * N_;
        float m = -1e30f;
        for (int i = lane; i < N_; i += 32) m = fmaxf(m, row[i]);
#pragma unroll
        for (int o = 16; o; o >>= 1) m = fmaxf(m, __shfl_xor_sync(0xffffffffu, m, o));
        float s = 0.f;
        for (int i = lane; i < N_; i += 32) {
            float e = __expf(row[i] - m);
            row[i] = e;
            s += e;
        }
#pragma unroll
        for (int o = 16; o; o >>= 1) s += __shfl_xor_sync(0xffffffffu, s, o);
        if (lane == 0) sinv[p * H_ + h] = __fdividef(1.f, s);
    }
    __syncthreads();

    {
        float iv[H_];
#pragma unroll
        for (int h = 0; h < H_; h++) iv[h] = sinv[p * H_ + h];
        float* gap = g_attn + ((long)(b * P_) + pg) * N_;
        for (int i = lane; i < 200; i += 32) {
            const int n = half * 200 + i;
            float a = 0.f;
#pragma unroll
            for (int h = 0; h < H_; h++) a = fmaf(scp[h * N_ + n], iv[h], a);
            gap[n] = a;
        }
    }
}

// ---------------------------------------------------------------------------
// Kernel C (pooling, v5): NO E staging — rows read straight from L2 with a
// 2-gene software pipeline; attn transposed gene-major so ONE broadcast
// LDS.128 yields all 4 pathway weights. Zero barriers in the main loop.
// Block = (b, 8 pathways), 256 threads; warp = (quad q, gene-quarter gq);
// each warp covers genes gq + 4j, j = 0..99 (no partial chunks).
//
// SMEM floats:
//   attnQ [0, 3200)       gene-major: [n][8 pathways]
//   red   [3200, 8000)    reduction scratch 24 x 50 u128
// = 32000 bytes -> 3 blocks/SM (reg-bound)
// ---------------------------------------------------------------------------
#define SMEM_C_FLOATS 8000
#define SMEM_C_BYTES  (SMEM_C_FLOATS * 4)

// load E row for vocab idx into (E0, E1) regs (E1 valid for lane<18)
#define LOAD_ROW(E0, E1, idx)                                           \
    do {                                                                \
        const ulonglong2* _r = egq + (long)(idx) * 50;                  \
        E0 = _r[lane];                                                  \
        if (lane < 18) E1 = _r[32 + lane];                              \
    } while (0)

// accumulate gene with row (E0,E1) and attn float4 av (4 pathways)
#define POOL_REG(E0, E1, av)                                            \
    do {                                                                \
        u64 v0 = pack2((av).x, (av).x);                                 \
        u64 v1 = pack2((av).y, (av).y);                                 \
        u64 v2 = pack2((av).z, (av).z);                                 \
        u64 v3 = pack2((av).w, (av).w);                                 \
        a00 = fma2((E0).x, v0, a00);  a01 = fma2((E0).y, v0, a01);      \
        a10 = fma2((E0).x, v1, a10);  a11 = fma2((E0).y, v1, a11);      \
        a20 = fma2((E0).x, v2, a20);  a21 = fma2((E0).y, v2, a21);      \
        a30 = fma2((E0).x, v3, a30);  a31 = fma2((E0).y, v3, a31);      \
        if (lane < 18) {                                                \
            a02 = fma2((E1).x, v0, a02);  a03 = fma2((E1).y, v0, a03);  \
            a12 = fma2((E1).x, v1, a12);  a13 = fma2((E1).y, v1, a13);  \
            a22 = fma2((E1).x, v2, a22);  a23 = fma2((E1).y, v2, a23);  \
            a32 = fma2((E1).x, v3, a32);  a33 = fma2((E1).y, v3, a33);  \
        }                                                               \
    } while (0)

__global__ __launch_bounds__(256, 3) void kC(
    const int* __restrict__ omc, const float* __restrict__ eg,
    float* __restrict__ out)
{
    float* attnQ = smemB;                        // [n*8 + p]
    ulonglong2* red = (ulonglong2*)(smemB + 3200);

    const int bx   = blockIdx.x;
    const int b    = bx / 25;
    const int pt8  = bx - b * 25;       // pathway octet
    const int t    = threadIdx.x;
    const int w    = t >> 5;
    const int lane = t & 31;
    const int q    = w >> 2;            // pathway quad 0..1
    const int gq   = w & 3;             // gene quarter

    const ulonglong2* egq = (const ulonglong2*)eg;   // 50 u128 per vocab row
    const int* omcb = omc + b * N_;

    // stage attn transposed: attnQ[n*8 + p] = g_attn[(b, pt8*8+p, n)]
    {
        const float* gA0 = g_attn + ((long)(b * P_) + pt8 * 8) * N_;
        for (int i = t; i < 3200; i += 256) {
            int n = i >> 3, p = i & 7;
            attnQ[n * 8 + p] = gA0[p * N_ + n];
        }
    }
    __syncthreads();

    const float4* aQ4 = (const float4*)attnQ;   // [n*2 + q]

    u64 a00=0, a01=0, a02=0, a03=0;
    u64 a10=0, a11=0, a12=0, a13=0;
    u64 a20=0, a21=0, a22=0, a23=0;
    u64 a30=0, a31=0, a32=0, a33=0;

    // software pipeline, depth 2: slots A (even j) and B (odd j)
    ulonglong2 eA0, eA1, eB0, eB1;
    eA1.x = eA1.y = eB1.x = eB1.y = 0ull;
    {
        int i0 = omcb[gq];
        int i1 = omcb[gq + 4];
        LOAD_ROW(eA0, eA1, i0);
        LOAD_ROW(eB0, eB1, i1);
    }

#pragma unroll 1
    for (int j = 0; j < 96; j += 2) {
        const int na = gq + 4 * j;
        int iN0 = omcb[na + 8];              // gene j+2
        int iN1 = omcb[na + 12];             // gene j+3
        float4 avA = aQ4[na * 2 + q];
        POOL_REG(eA0, eA1, avA);
        LOAD_ROW(eA0, eA1, iN0);
        float4 avB = aQ4[(na + 4) * 2 + q];
        POOL_REG(eB0, eB1, avB);
        LOAD_ROW(eB0, eB1, iN1);
    }
    // epilogue: genes 96, 97 in A/B; load + compute 98, 99
    {
        const int na = gq + 4 * 96;
        float4 avA = aQ4[na * 2 + q];
        POOL_REG(eA0, eA1, avA);
        int i98 = omcb[na + 8];
        LOAD_ROW(eA0, eA1, i98);
        float4 avB = aQ4[(na + 4) * 2 + q];
        POOL_REG(eB0, eB1, avB);
        int i99 = omcb[na + 12];
        LOAD_ROW(eB0, eB1, i99);
        float4 av98 = aQ4[(na + 8) * 2 + q];
        POOL_REG(eA0, eA1, av98);
        float4 av99 = aQ4[(na + 12) * 2 + q];
        POOL_REG(eB0, eB1, av99);
    }
    __syncthreads();   // attnQ reads done; smem free for reduction

    // reduction over gene-quarters via smem.
    // red layout: [(q*3 + (gq-1))*4 + p] rows of 50 u128 -> 24 x 50 u128
    if (gq != 0) {
        ulonglong2* r0 = red + ((q * 3 + (gq - 1)) * 4 + 0) * 50;
        ulonglong2* r1 = red + ((q * 3 + (gq - 1)) * 4 + 1) * 50;
        ulonglong2* r2 = red + ((q * 3 + (gq - 1)) * 4 + 2) * 50;
        ulonglong2* r3 = red + ((q * 3 + (gq - 1)) * 4 + 3) * 50;
        ulonglong2 s;
        s.x = a00; s.y = a01; r0[lane] = s;
        s.x = a10; s.y = a11; r1[lane] = s;
        s.x = a20; s.y = a21; r2[lane] = s;
        s.x = a30; s.y = a31; r3[lane] = s;
        if (lane < 18) {
            s.x = a02; s.y = a03; r0[32 + lane] = s;
            s.x = a12; s.y = a13; r1[32 + lane] = s;
            s.x = a22; s.y = a23; r2[32 + lane] = s;
            s.x = a32; s.y = a33; r3[32 + lane] = s;
        }
    }
    __syncthreads();
    if (gq == 0) {
#pragma unroll
        for (int j = 0; j < 3; j++) {
            const ulonglong2* r0 = red + ((q * 3 + j) * 4 + 0) * 50;
            const ulonglong2* r1 = red + ((q * 3 + j) * 4 + 1) * 50;
            const ulonglong2* r2 = red + ((q * 3 + j) * 4 + 2) * 50;
            const ulonglong2* r3 = red + ((q * 3 + j) * 4 + 3) * 50;
            ulonglong2 s;
            s = r0[lane]; a00 = add2(a00, s.x); a01 = add2(a01, s.y);
            s = r1[lane]; a10 = add2(a10, s.x); a11 = add2(a11, s.y);
            s = r2[lane]; a20 = add2(a20, s.x); a21 = add2(a21, s.y);
            s = r3[lane]; a30 = add2(a30, s.x); a31 = add2(a31, s.y);
            if (lane < 18) {
                s = r0[32 + lane]; a02 = add2(a02, s.x); a03 = add2(a03, s.y);
                s = r1[32 + lane]; a12 = add2(a12, s.x); a13 = add2(a13, s.y);
                s = r2[32 + lane]; a22 = add2(a22, s.x); a23 = add2(a23, s.y);
                s = r3[32 + lane]; a32 = add2(a32, s.x); a33 = add2(a33, s.y);
            }
        }
        const int pg0 = pt8 * 8 + q * 4;
        ulonglong2* op0 = (ulonglong2*)(out + (long)(b * P_ + pg0 + 0) * E_D);
        ulonglong2* op1 = (ulonglong2*)(out + (long)(b * P_ + pg0 + 1) * E_D);
        ulonglong2* op2 = (ulonglong2*)(out + (long)(b * P_ + pg0 + 2) * E_D);
        ulonglong2* op3 = (ulonglong2*)(out + (long)(b * P_ + pg0 + 3) * E_D);
        ulonglong2 s;
        s.x = a00; s.y = a01; op0[lane] = s;
        s.x = a10; s.y = a11; op1[lane] = s;
        s.x = a20; s.y = a21; op2[lane] = s;
        s.x = a30; s.y = a31; op3[lane] = s;
        if (lane < 18) {
            s.x = a02; s.y = a03; op0[32 + lane] = s;
            s.x = a12; s.y = a13; op1[32 + lane] = s;
            s.x = a22; s.y = a23; op2[32 + lane] = s;
            s.x = a32; s.y = a33; op3[32 + lane] = s;
        }
    }
}

// ---------------------------------------------------------------------------
extern "C" void kernel_launch(void* const* d_in, const int* in_sizes, int n_in,
                              void* d_out, int out_size)
{
    const int*   omc = (const int*)  d_in[0];
    const int*   ptw = (const int*)  d_in[1];
    const float* eg  = (const float*)d_in[2];
    const float* ept = (const float*)d_in[3];
    const float* W0  = (const float*)d_in[4];
    const float* b0  = (const float*)d_in[5];
    const float* Wb  = (const float*)d_in[6];
    const float* bb  = (const float*)d_in[7];
    float* out = (float*)d_out;

    kW<<<4, 256>>>(Wb);
    void* srcp = nullptr;
    cudaGetSymbolAddress(&srcp, g_wbDup);
    void* dstp = nullptr;
    cudaGetSymbolAddress(&dstp, c_wb4);
    cudaMemcpyAsync(dstp, srcp, sizeof(u64) * A_D * H_,
                    cudaMemcpyDeviceToDevice, 0);

    kA<<<(B_ * N_) / 8, 128>>>(omc, eg, W0, b0);

    cudaFuncSetAttribute(kB, cudaFuncAttributeMaxDynamicSharedMemorySize,
                         SMEM_B_BYTES);
    kB<<<B_ * (P_ / PT), 256, SMEM_B_BYTES>>>(ptw, ept, Wb, bb);

    cudaFuncSetAttribute(kC, cudaFuncAttributeMaxDynamicSharedMemorySize,
                         SMEM_C_BYTES);
    kC<<<B_ * (P_ / 8), 256, SMEM_C_BYTES>>>(omc, eg, out);
}